// round 1
// baseline (speedup 1.0000x reference)
#include <cuda_runtime.h>
#include <cuda_bf16.h>
#include <cstdint>
#include <cstddef>

// Problem constants
#define BB   2
#define SS   2048
#define DD   2048
#define HH   16
#define KVHH 4
#define HDD  128
#define GG   4   // H / KVH

// ---------------------------------------------------------------------------
// Scratch (device globals — no allocations allowed)
// ---------------------------------------------------------------------------
__device__ float g_q[BB * SS * HH * HDD];      // [B,S,H,HD]   33.5 MB
__device__ float g_k[BB * SS * KVHH * HDD];    // [B,S,KVH,HD]  8.4 MB
__device__ float g_v[BB * SS * KVHH * HDD];    // [B,S,KVH,HD]  8.4 MB
__device__ float g_ctx[BB * SS * HH * HDD];    // [B,S,H,HD]   33.5 MB

// ---------------------------------------------------------------------------
// SGEMM: C[M,N] = A[M,K] @ B[K,N], row-major, fp32.
// 128x128 block tile, BK=8, 256 threads, 8x8 per-thread tile, double-buffered.
// M % 128 == 0, N % 128 == 0, K % 8 == 0 (true for all our shapes).
// ---------------------------------------------------------------------------
__global__ __launch_bounds__(256, 2) void sgemm_kernel(
    const float* __restrict__ A, const float* __restrict__ B,
    float* __restrict__ C, int M, int N, int K)
{
    __shared__ float As[2][8][128];
    __shared__ float Bs[2][8][128];

    const int tid  = threadIdx.x;
    const int arow = tid >> 1;            // 0..127
    const int acol = (tid & 1) << 2;      // 0 or 4
    const int brow = tid >> 5;            // 0..7
    const int bcol = (tid & 31) << 2;     // 0..124

    const float* Ap = A + (size_t)(blockIdx.y * 128 + arow) * K + acol;
    const float* Bp = B + (size_t)brow * N + blockIdx.x * 128 + bcol;

    const int tm = (tid >> 4) << 3;       // 0..120
    const int tn = (tid & 15) << 3;       // 0..120

    float acc[8][8];
    #pragma unroll
    for (int i = 0; i < 8; i++)
        #pragma unroll
        for (int j = 0; j < 8; j++) acc[i][j] = 0.f;

    // preload tile 0
    float4 a4 = *(const float4*)Ap;
    float4 b4 = *(const float4*)Bp;
    As[0][acol + 0][arow] = a4.x;
    As[0][acol + 1][arow] = a4.y;
    As[0][acol + 2][arow] = a4.z;
    As[0][acol + 3][arow] = a4.w;
    *(float4*)&Bs[0][brow][bcol] = b4;
    __syncthreads();

    int buf = 0;
    for (int k0 = 8; k0 <= K; k0 += 8) {
        if (k0 < K) {
            a4 = *(const float4*)(Ap + k0);
            b4 = *(const float4*)(Bp + (size_t)k0 * N);
        }
        #pragma unroll
        for (int kk = 0; kk < 8; kk++) {
            float ra[8], rb[8];
            *(float4*)&ra[0] = *(const float4*)&As[buf][kk][tm];
            *(float4*)&ra[4] = *(const float4*)&As[buf][kk][tm + 4];
            *(float4*)&rb[0] = *(const float4*)&Bs[buf][kk][tn];
            *(float4*)&rb[4] = *(const float4*)&Bs[buf][kk][tn + 4];
            #pragma unroll
            for (int i = 0; i < 8; i++)
                #pragma unroll
                for (int j = 0; j < 8; j++)
                    acc[i][j] += ra[i] * rb[j];
        }
        if (k0 < K) {
            const int nb = buf ^ 1;
            As[nb][acol + 0][arow] = a4.x;
            As[nb][acol + 1][arow] = a4.y;
            As[nb][acol + 2][arow] = a4.z;
            As[nb][acol + 3][arow] = a4.w;
            *(float4*)&Bs[nb][brow][bcol] = b4;
        }
        __syncthreads();
        buf ^= 1;
    }

    float* Cp = C + (size_t)(blockIdx.y * 128 + tm) * N + blockIdx.x * 128 + tn;
    #pragma unroll
    for (int i = 0; i < 8; i++) {
        *(float4*)&Cp[(size_t)i * N]     = make_float4(acc[i][0], acc[i][1], acc[i][2], acc[i][3]);
        *(float4*)&Cp[(size_t)i * N + 4] = make_float4(acc[i][4], acc[i][5], acc[i][6], acc[i][7]);
    }
}

// ---------------------------------------------------------------------------
// RoPE: in-place on x laid out [B, S, heads, HD].
// For i in [0,64): out[i]    = x[i]*cos[i]    - x[i+64]*sin[i]
//                  out[i+64] = x[i+64]*cos[i+64] + x[i]*sin[i+64]
// One thread per (b,s,h,pair). Grid covers exactly B*S*heads*64 threads.
// ---------------------------------------------------------------------------
__global__ void rope_kernel(float* __restrict__ x,
                            const float* __restrict__ cosT,
                            const float* __restrict__ sinT, int heads)
{
    const int idx  = blockIdx.x * blockDim.x + threadIdx.x;
    const int half = idx & 63;
    const int h    = (idx >> 6) % heads;
    const int s    = (idx / (64 * heads)) % SS;
    const int b    = idx / (64 * heads * SS);

    float* p = x + (size_t)((b * SS + s) * heads + h) * HDD;
    const float x1 = p[half];
    const float x2 = p[half + 64];
    const float c1 = cosT[s * HDD + half];
    const float s1 = sinT[s * HDD + half];
    const float c2 = cosT[s * HDD + half + 64];
    const float s2 = sinT[s * HDD + half + 64];
    p[half]      = x1 * c1 - x2 * s1;
    p[half + 64] = x2 * c2 + x1 * s2;
}

// ---------------------------------------------------------------------------
// Flash-style causal attention with alibi + mask.
// Grid: (S/64, B*H). 256 threads. BM=BN=64, HD=128. Online softmax.
// q: [B,S,H,HD] (pre-RoPE'd, scaled here), k/v: [B,S,KVH,HD], ctx: [B,S,H,HD].
// ---------------------------------------------------------------------------
struct AttSmem {
    float Qs[64][132];   // padded: stride 132 floats (16B-aligned rows)
    float Ks[64][132];
    float Vs[64][128];
    float Sc[64][65];
    float Red[4][64];
    float RedS[4][64];
};

__global__ __launch_bounds__(256) void attn_kernel(
    const float* __restrict__ q, const float* __restrict__ k,
    const float* __restrict__ v, const float* __restrict__ alibi,
    const float* __restrict__ mask, float* __restrict__ ctx)
{
    extern __shared__ char smem_raw[];
    AttSmem& sm = *reinterpret_cast<AttSmem*>(smem_raw);

    const int tid   = threadIdx.x;
    const int qtile = blockIdx.x;
    const int bh    = blockIdx.y;
    const int b     = bh / HH;
    const int h     = bh % HH;
    const int kh    = h / GG;
    const int q0    = qtile * 64;

    const float scale = 0.08838834764831845f;  // 1/sqrt(128)

    // load Q tile (pre-scaled)
    #pragma unroll
    for (int i = 0; i < 8; i++) {
        const int idx = tid + i * 256;   // 0..2047
        const int r   = idx >> 5;
        const int c4  = (idx & 31) << 2;
        const float4 a = *(const float4*)(q + (size_t)((b * SS + q0 + r) * HH + h) * HDD + c4);
        float* dst = &sm.Qs[r][c4];
        dst[0] = a.x * scale; dst[1] = a.y * scale;
        dst[2] = a.z * scale; dst[3] = a.w * scale;
    }

    float O[32];
    #pragma unroll
    for (int j = 0; j < 32; j++) O[j] = 0.f;
    float m_i = -1e30f, l_i = 0.f;

    const int row = tid & 63;         // softmax / PV row ownership
    const int q4  = tid >> 6;         // quarter (col group)
    const int rr  = (tid >> 4) << 2;  // score-phase 4x4 tile coords
    const int cc  = (tid & 15) << 2;

    const int ntiles = qtile + 1;     // causal: only kv tiles <= q tile
    for (int t = 0; t < ntiles; t++) {
        const int kv0 = t * 64;
        __syncthreads();  // protect Ks/Vs from previous iteration's readers

        // load K and V tiles
        #pragma unroll
        for (int i = 0; i < 8; i++) {
            const int idx = tid + i * 256;
            const int r   = idx >> 5;
            const int c4  = (idx & 31) << 2;
            const size_t base = (size_t)((b * SS + kv0 + r) * KVHH + kh) * HDD + c4;
            *(float4*)&sm.Ks[r][c4] = *(const float4*)(k + base);
            *(float4*)&sm.Vs[r][c4] = *(const float4*)(v + base);
        }
        __syncthreads();

        // scores: each thread computes a 4x4 block of the 64x64 tile
        float sc[4][4];
        #pragma unroll
        for (int i = 0; i < 4; i++)
            #pragma unroll
            for (int j = 0; j < 4; j++) sc[i][j] = 0.f;

        #pragma unroll 8
        for (int kk = 0; kk < HDD; kk += 4) {
            float4 qa[4], kb[4];
            #pragma unroll
            for (int i = 0; i < 4; i++) qa[i] = *(const float4*)&sm.Qs[rr + i][kk];
            #pragma unroll
            for (int j = 0; j < 4; j++) kb[j] = *(const float4*)&sm.Ks[cc + j][kk];
            #pragma unroll
            for (int i = 0; i < 4; i++)
                #pragma unroll
                for (int j = 0; j < 4; j++)
                    sc[i][j] += qa[i].x * kb[j].x + qa[i].y * kb[j].y
                              + qa[i].z * kb[j].z + qa[i].w * kb[j].w;
        }

        // bias + causal; write scores to smem
        #pragma unroll
        for (int i = 0; i < 4; i++) {
            const int qg = q0 + rr + i;
            #pragma unroll
            for (int j = 0; j < 4; j++) {
                const int kg = kv0 + cc + j;
                float s;
                if (kg > qg) {
                    s = -1e30f;   // exp underflows to exactly 0, matching ref's -1e9 mask
                } else {
                    s = sc[i][j] + alibi[((size_t)b * SS + qg) * SS + kg]
                                 + mask[b * SS + kg];
                }
                sm.Sc[rr + i][cc + j] = s;
            }
        }
        __syncthreads();

        // online softmax: partial row max
        float lm = -1e30f;
        #pragma unroll
        for (int j = 0; j < 16; j++) lm = fmaxf(lm, sm.Sc[row][q4 * 16 + j]);
        sm.Red[q4][row] = lm;
        __syncthreads();

        const float rowmax = fmaxf(fmaxf(sm.Red[0][row], sm.Red[1][row]),
                                   fmaxf(sm.Red[2][row], sm.Red[3][row]));
        const float newm = fmaxf(m_i, rowmax);
        const float fac  = __expf(m_i - newm);

        float ls = 0.f;
        #pragma unroll
        for (int j = 0; j < 16; j++) {
            const float p = __expf(sm.Sc[row][q4 * 16 + j] - newm);
            sm.Sc[row][q4 * 16 + j] = p;
            ls += p;
        }
        sm.RedS[q4][row] = ls;

        #pragma unroll
        for (int j = 0; j < 32; j++) O[j] *= fac;
        m_i = newm;
        __syncthreads();

        l_i = l_i * fac + sm.RedS[0][row] + sm.RedS[1][row]
                        + sm.RedS[2][row] + sm.RedS[3][row];

        // O += P @ V   (thread owns row `row`, cols [q4*32, q4*32+32))
        const int cbase = q4 * 32;
        for (int c = 0; c < 64; c++) {
            const float p = sm.Sc[row][c];
            #pragma unroll
            for (int j4 = 0; j4 < 8; j4++) {
                const float4 vv = *(const float4*)&sm.Vs[c][cbase + j4 * 4];
                O[j4 * 4 + 0] += p * vv.x;
                O[j4 * 4 + 1] += p * vv.y;
                O[j4 * 4 + 2] += p * vv.z;
                O[j4 * 4 + 3] += p * vv.w;
            }
        }
    }

    // normalize + write
    const float inv_l = 1.f / l_i;
    float* dst = ctx + (size_t)((b * SS + q0 + row) * HH + h) * HDD + q4 * 32;
    #pragma unroll
    for (int j4 = 0; j4 < 8; j4++) {
        *(float4*)&dst[j4 * 4] = make_float4(O[j4 * 4 + 0] * inv_l,
                                             O[j4 * 4 + 1] * inv_l,
                                             O[j4 * 4 + 2] * inv_l,
                                             O[j4 * 4 + 3] * inv_l);
    }
}

// ---------------------------------------------------------------------------
// Launch
// ---------------------------------------------------------------------------
extern "C" void kernel_launch(void* const* d_in, const int* in_sizes, int n_in,
                              void* d_out, int out_size)
{
    const float* hs    = (const float*)d_in[0];
    const float* cosT  = (const float*)d_in[1];
    const float* sinT  = (const float*)d_in[2];
    const float* alibi = (const float*)d_in[3];
    const float* mask  = (const float*)d_in[4];
    const float* wq    = (const float*)d_in[5];
    const float* wk    = (const float*)d_in[6];
    const float* wv    = (const float*)d_in[7];
    const float* wo    = (const float*)d_in[8];
    float* out = (float*)d_out;

    float *qb, *kb, *vb, *cb;
    cudaGetSymbolAddress((void**)&qb, g_q);
    cudaGetSymbolAddress((void**)&kb, g_k);
    cudaGetSymbolAddress((void**)&vb, g_v);
    cudaGetSymbolAddress((void**)&cb, g_ctx);

    const int M = BB * SS;  // 4096

    // QKV projections
    {
        dim3 gq(DD / 128, M / 128);              // 16 x 32
        sgemm_kernel<<<gq, 256>>>(hs, wq, qb, M, DD, DD);
        dim3 gkv((KVHH * HDD) / 128, M / 128);   // 4 x 32
        sgemm_kernel<<<gkv, 256>>>(hs, wk, kb, M, KVHH * HDD, DD);
        sgemm_kernel<<<gkv, 256>>>(hs, wv, vb, M, KVHH * HDD, DD);
    }

    // RoPE on Q (16 heads) and K (4 heads)
    {
        const int tq = BB * SS * HH * 64;    // 4,194,304
        rope_kernel<<<tq / 256, 256>>>(qb, cosT, sinT, HH);
        const int tk = BB * SS * KVHH * 64;  // 1,048,576
        rope_kernel<<<tk / 256, 256>>>(kb, cosT, sinT, KVHH);
    }

    // Attention
    {
        static_assert(sizeof(AttSmem) <= 220 * 1024, "smem too big");
        cudaFuncSetAttribute(attn_kernel,
                             cudaFuncAttributeMaxDynamicSharedMemorySize,
                             (int)sizeof(AttSmem));
        dim3 ga(SS / 64, BB * HH);           // 32 x 32
        attn_kernel<<<ga, 256, sizeof(AttSmem)>>>(qb, kb, vb, alibi, mask, cb);
    }

    // Output projection -> d_out
    {
        dim3 go(DD / 128, M / 128);          // 16 x 32
        sgemm_kernel<<<go, 256>>>(cb, wo, out, M, DD, DD);
    }
}

// round 2
// speedup vs baseline: 1.5448x; 1.5448x over previous
#include <cuda_runtime.h>
#include <cuda_bf16.h>
#include <cstdint>
#include <cstddef>

// Problem constants
#define BB   2
#define SS   2048
#define DD   2048
#define HH   16
#define KVHH 4
#define HDD  128
#define GG   4   // H / KVH

// ---------------------------------------------------------------------------
// Scratch (device globals — no allocations allowed)
// ---------------------------------------------------------------------------
__device__ float g_q[BB * SS * HH * HDD];      // [B,S,H,HD]   33.5 MB
__device__ float g_k[BB * SS * KVHH * HDD];    // [B,S,KVH,HD]  8.4 MB
__device__ float g_v[BB * SS * KVHH * HDD];    // [B,S,KVH,HD]  8.4 MB
__device__ float g_ctx[BB * SS * HH * HDD];    // [B,S,H,HD]   33.5 MB

// ---------------------------------------------------------------------------
// TF32 tensor-core GEMM: C[M,N] = A[M,K] @ B[K,N], row-major fp32 in/out.
// 128x128 block tile, BK=32, 256 threads (8 warps, 2x4 grid, 64x32 warp tile).
// mma.sync.m16n8k8.tf32 with fp32 accumulate. RNA rounding to tf32 at smem
// store time. M%128==0, N%128==0, K%32==0 (true for all our shapes).
// ---------------------------------------------------------------------------
__device__ __forceinline__ uint32_t f2tf(float x) {
    uint32_t u;
    asm("cvt.rna.tf32.f32 %0, %1;" : "=r"(u) : "f"(x));
    return u;
}

__device__ __forceinline__ void mma16x8x8(float* c, const uint32_t* a,
                                          const uint32_t* b) {
    asm volatile(
        "mma.sync.aligned.m16n8k8.row.col.f32.tf32.tf32.f32 "
        "{%0,%1,%2,%3}, {%4,%5,%6,%7}, {%8,%9}, {%0,%1,%2,%3};\n"
        : "+f"(c[0]), "+f"(c[1]), "+f"(c[2]), "+f"(c[3])
        : "r"(a[0]), "r"(a[1]), "r"(a[2]), "r"(a[3]), "r"(b[0]), "r"(b[1]));
}

__global__ __launch_bounds__(256, 2) void tf32_gemm_kernel(
    const float* __restrict__ A, const float* __restrict__ B,
    float* __restrict__ C, int M, int N, int K)
{
    __shared__ uint32_t As[128][36];   // [m][k], pad 36: conflict-free frag loads
    __shared__ uint32_t Bs[32][136];   // [k][n], pad 136

    const int tid  = threadIdx.x;
    const int lane = tid & 31;
    const int warp = tid >> 5;
    const int wm   = (warp >> 2) * 64;   // warp M offset (0 or 64)
    const int wn   = (warp & 3) * 32;    // warp N offset (0,32,64,96)
    const int grp  = lane >> 2;          // 0..7
    const int qid  = lane & 3;           // 0..3
    const int bm   = blockIdx.y * 128;
    const int bn   = blockIdx.x * 128;

    float c[4][4][4];
    #pragma unroll
    for (int mi = 0; mi < 4; mi++)
        #pragma unroll
        for (int ni = 0; ni < 4; ni++)
            #pragma unroll
            for (int r = 0; r < 4; r++) c[mi][ni][r] = 0.f;

    for (int k0 = 0; k0 < K; k0 += 32) {
        __syncthreads();
        // load A[128,32] and B[32,128] tiles, convert to tf32
        #pragma unroll
        for (int i = 0; i < 4; i++) {
            const int idx = tid + i * 256;
            const int ar  = idx >> 3;
            const int ac  = (idx & 7) << 2;
            const float4 va = *(const float4*)(A + (size_t)(bm + ar) * K + k0 + ac);
            uint4 ua;
            ua.x = f2tf(va.x); ua.y = f2tf(va.y);
            ua.z = f2tf(va.z); ua.w = f2tf(va.w);
            *(uint4*)&As[ar][ac] = ua;

            const int br = idx >> 5;
            const int bc = (idx & 31) << 2;
            const float4 vb = *(const float4*)(B + (size_t)(k0 + br) * N + bn + bc);
            uint4 ub;
            ub.x = f2tf(vb.x); ub.y = f2tf(vb.y);
            ub.z = f2tf(vb.z); ub.w = f2tf(vb.w);
            *(uint4*)&Bs[br][bc] = ub;
        }
        __syncthreads();

        #pragma unroll
        for (int kk = 0; kk < 32; kk += 8) {
            uint32_t a[4][4], b[4][2];
            #pragma unroll
            for (int mi = 0; mi < 4; mi++) {
                const int m = wm + mi * 16 + grp;
                a[mi][0] = As[m][kk + qid];
                a[mi][1] = As[m + 8][kk + qid];
                a[mi][2] = As[m][kk + qid + 4];
                a[mi][3] = As[m + 8][kk + qid + 4];
            }
            #pragma unroll
            for (int ni = 0; ni < 4; ni++) {
                const int n = wn + ni * 8 + grp;
                b[ni][0] = Bs[kk + qid][n];
                b[ni][1] = Bs[kk + qid + 4][n];
            }
            #pragma unroll
            for (int mi = 0; mi < 4; mi++)
                #pragma unroll
                for (int ni = 0; ni < 4; ni++)
                    mma16x8x8(c[mi][ni], a[mi], b[ni]);
        }
    }

    // epilogue: each frag row pair -> float2 stores
    #pragma unroll
    for (int mi = 0; mi < 4; mi++) {
        const int row0 = bm + wm + mi * 16 + grp;
        #pragma unroll
        for (int ni = 0; ni < 4; ni++) {
            const int col = bn + wn + ni * 8 + qid * 2;
            *(float2*)&C[(size_t)row0 * N + col] =
                make_float2(c[mi][ni][0], c[mi][ni][1]);
            *(float2*)&C[(size_t)(row0 + 8) * N + col] =
                make_float2(c[mi][ni][2], c[mi][ni][3]);
        }
    }
}

// ---------------------------------------------------------------------------
// RoPE: in-place on x laid out [B, S, heads, HD].
// ---------------------------------------------------------------------------
__global__ void rope_kernel(float* __restrict__ x,
                            const float* __restrict__ cosT,
                            const float* __restrict__ sinT, int heads)
{
    const int idx  = blockIdx.x * blockDim.x + threadIdx.x;
    const int half = idx & 63;
    const int h    = (idx >> 6) % heads;
    const int s    = (idx / (64 * heads)) % SS;
    const int b    = idx / (64 * heads * SS);

    float* p = x + (size_t)((b * SS + s) * heads + h) * HDD;
    const float x1 = p[half];
    const float x2 = p[half + 64];
    const float c1 = cosT[s * HDD + half];
    const float s1 = sinT[s * HDD + half];
    const float c2 = cosT[s * HDD + half + 64];
    const float s2 = sinT[s * HDD + half + 64];
    p[half]      = x1 * c1 - x2 * s1;
    p[half + 64] = x2 * c2 + x1 * s2;
}

// ---------------------------------------------------------------------------
// Flash-style causal attention with alibi + mask (fp32, unchanged).
// Grid: (S/64, B*H). 256 threads. BM=BN=64, HD=128. Online softmax.
// ---------------------------------------------------------------------------
struct AttSmem {
    float Qs[64][132];
    float Ks[64][132];
    float Vs[64][128];
    float Sc[64][65];
    float Red[4][64];
    float RedS[4][64];
};

__global__ __launch_bounds__(256) void attn_kernel(
    const float* __restrict__ q, const float* __restrict__ k,
    const float* __restrict__ v, const float* __restrict__ alibi,
    const float* __restrict__ mask, float* __restrict__ ctx)
{
    extern __shared__ char smem_raw[];
    AttSmem& sm = *reinterpret_cast<AttSmem*>(smem_raw);

    const int tid   = threadIdx.x;
    const int qtile = blockIdx.x;
    const int bh    = blockIdx.y;
    const int b     = bh / HH;
    const int h     = bh % HH;
    const int kh    = h / GG;
    const int q0    = qtile * 64;

    const float scale = 0.08838834764831845f;  // 1/sqrt(128)

    #pragma unroll
    for (int i = 0; i < 8; i++) {
        const int idx = tid + i * 256;
        const int r   = idx >> 5;
        const int c4  = (idx & 31) << 2;
        const float4 a = *(const float4*)(q + (size_t)((b * SS + q0 + r) * HH + h) * HDD + c4);
        float* dst = &sm.Qs[r][c4];
        dst[0] = a.x * scale; dst[1] = a.y * scale;
        dst[2] = a.z * scale; dst[3] = a.w * scale;
    }

    float O[32];
    #pragma unroll
    for (int j = 0; j < 32; j++) O[j] = 0.f;
    float m_i = -1e30f, l_i = 0.f;

    const int row = tid & 63;
    const int q4  = tid >> 6;
    const int rr  = (tid >> 4) << 2;
    const int cc  = (tid & 15) << 2;

    const int ntiles = qtile + 1;
    for (int t = 0; t < ntiles; t++) {
        const int kv0 = t * 64;
        __syncthreads();

        #pragma unroll
        for (int i = 0; i < 8; i++) {
            const int idx = tid + i * 256;
            const int r   = idx >> 5;
            const int c4  = (idx & 31) << 2;
            const size_t base = (size_t)((b * SS + kv0 + r) * KVHH + kh) * HDD + c4;
            *(float4*)&sm.Ks[r][c4] = *(const float4*)(k + base);
            *(float4*)&sm.Vs[r][c4] = *(const float4*)(v + base);
        }
        __syncthreads();

        float sc[4][4];
        #pragma unroll
        for (int i = 0; i < 4; i++)
            #pragma unroll
            for (int j = 0; j < 4; j++) sc[i][j] = 0.f;

        #pragma unroll 8
        for (int kk = 0; kk < HDD; kk += 4) {
            float4 qa[4], kb[4];
            #pragma unroll
            for (int i = 0; i < 4; i++) qa[i] = *(const float4*)&sm.Qs[rr + i][kk];
            #pragma unroll
            for (int j = 0; j < 4; j++) kb[j] = *(const float4*)&sm.Ks[cc + j][kk];
            #pragma unroll
            for (int i = 0; i < 4; i++)
                #pragma unroll
                for (int j = 0; j < 4; j++)
                    sc[i][j] += qa[i].x * kb[j].x + qa[i].y * kb[j].y
                              + qa[i].z * kb[j].z + qa[i].w * kb[j].w;
        }

        #pragma unroll
        for (int i = 0; i < 4; i++) {
            const int qg = q0 + rr + i;
            #pragma unroll
            for (int j = 0; j < 4; j++) {
                const int kg = kv0 + cc + j;
                float s;
                if (kg > qg) {
                    s = -1e30f;
                } else {
                    s = sc[i][j] + alibi[((size_t)b * SS + qg) * SS + kg]
                                 + mask[b * SS + kg];
                }
                sm.Sc[rr + i][cc + j] = s;
            }
        }
        __syncthreads();

        float lm = -1e30f;
        #pragma unroll
        for (int j = 0; j < 16; j++) lm = fmaxf(lm, sm.Sc[row][q4 * 16 + j]);
        sm.Red[q4][row] = lm;
        __syncthreads();

        const float rowmax = fmaxf(fmaxf(sm.Red[0][row], sm.Red[1][row]),
                                   fmaxf(sm.Red[2][row], sm.Red[3][row]));
        const float newm = fmaxf(m_i, rowmax);
        const float fac  = __expf(m_i - newm);

        float ls = 0.f;
        #pragma unroll
        for (int j = 0; j < 16; j++) {
            const float p = __expf(sm.Sc[row][q4 * 16 + j] - newm);
            sm.Sc[row][q4 * 16 + j] = p;
            ls += p;
        }
        sm.RedS[q4][row] = ls;

        #pragma unroll
        for (int j = 0; j < 32; j++) O[j] *= fac;
        m_i = newm;
        __syncthreads();

        l_i = l_i * fac + sm.RedS[0][row] + sm.RedS[1][row]
                        + sm.RedS[2][row] + sm.RedS[3][row];

        const int cbase = q4 * 32;
        for (int c = 0; c < 64; c++) {
            const float p = sm.Sc[row][c];
            #pragma unroll
            for (int j4 = 0; j4 < 8; j4++) {
                const float4 vv = *(const float4*)&sm.Vs[c][cbase + j4 * 4];
                O[j4 * 4 + 0] += p * vv.x;
                O[j4 * 4 + 1] += p * vv.y;
                O[j4 * 4 + 2] += p * vv.z;
                O[j4 * 4 + 3] += p * vv.w;
            }
        }
    }

    const float inv_l = 1.f / l_i;
    float* dst = ctx + (size_t)((b * SS + q0 + row) * HH + h) * HDD + q4 * 32;
    #pragma unroll
    for (int j4 = 0; j4 < 8; j4++) {
        *(float4*)&dst[j4 * 4] = make_float4(O[j4 * 4 + 0] * inv_l,
                                             O[j4 * 4 + 1] * inv_l,
                                             O[j4 * 4 + 2] * inv_l,
                                             O[j4 * 4 + 3] * inv_l);
    }
}

// ---------------------------------------------------------------------------
// Launch
// ---------------------------------------------------------------------------
extern "C" void kernel_launch(void* const* d_in, const int* in_sizes, int n_in,
                              void* d_out, int out_size)
{
    const float* hs    = (const float*)d_in[0];
    const float* cosT  = (const float*)d_in[1];
    const float* sinT  = (const float*)d_in[2];
    const float* alibi = (const float*)d_in[3];
    const float* mask  = (const float*)d_in[4];
    const float* wq    = (const float*)d_in[5];
    const float* wk    = (const float*)d_in[6];
    const float* wv    = (const float*)d_in[7];
    const float* wo    = (const float*)d_in[8];
    float* out = (float*)d_out;

    float *qb, *kb, *vb, *cb;
    cudaGetSymbolAddress((void**)&qb, g_q);
    cudaGetSymbolAddress((void**)&kb, g_k);
    cudaGetSymbolAddress((void**)&vb, g_v);
    cudaGetSymbolAddress((void**)&cb, g_ctx);

    const int M = BB * SS;  // 4096

    // QKV projections (tf32 tensor cores)
    {
        dim3 gq(DD / 128, M / 128);              // 16 x 32
        tf32_gemm_kernel<<<gq, 256>>>(hs, wq, qb, M, DD, DD);
        dim3 gkv((KVHH * HDD) / 128, M / 128);   // 4 x 32
        tf32_gemm_kernel<<<gkv, 256>>>(hs, wk, kb, M, KVHH * HDD, DD);
        tf32_gemm_kernel<<<gkv, 256>>>(hs, wv, vb, M, KVHH * HDD, DD);
    }

    // RoPE on Q (16 heads) and K (4 heads)
    {
        const int tq = BB * SS * HH * 64;
        rope_kernel<<<tq / 256, 256>>>(qb, cosT, sinT, HH);
        const int tk = BB * SS * KVHH * 64;
        rope_kernel<<<tk / 256, 256>>>(kb, cosT, sinT, KVHH);
    }

    // Attention (fp32)
    {
        static_assert(sizeof(AttSmem) <= 220 * 1024, "smem too big");
        cudaFuncSetAttribute(attn_kernel,
                             cudaFuncAttributeMaxDynamicSharedMemorySize,
                             (int)sizeof(AttSmem));
        dim3 ga(SS / 64, BB * HH);
        attn_kernel<<<ga, 256, sizeof(AttSmem)>>>(qb, kb, vb, alibi, mask, cb);
    }

    // Output projection -> d_out (tf32 tensor cores)
    {
        dim3 go(DD / 128, M / 128);
        tf32_gemm_kernel<<<go, 256>>>(cb, wo, out, M, DD, DD);
    }
}

// round 3
// speedup vs baseline: 3.4130x; 2.2093x over previous
#include <cuda_runtime.h>
#include <cuda_bf16.h>
#include <cstdint>
#include <cstddef>

// Problem constants
#define BB   2
#define SS   2048
#define DD   2048
#define HH   16
#define KVHH 4
#define HDD  128
#define GG   4   // H / KVH

// ---------------------------------------------------------------------------
// Scratch (device globals — no allocations allowed)
// ---------------------------------------------------------------------------
__device__ float g_q[BB * SS * HH * HDD];      // [B,S,H,HD]
__device__ float g_k[BB * SS * KVHH * HDD];    // [B,S,KVH,HD]
__device__ float g_v[BB * SS * KVHH * HDD];    // [B,S,KVH,HD]
__device__ float g_ctx[BB * SS * HH * HDD];    // [B,S,H,HD]

// ---------------------------------------------------------------------------
// tf32 helpers
// ---------------------------------------------------------------------------
__device__ __forceinline__ uint32_t f2tf(float x) {
    uint32_t u;
    asm("cvt.rna.tf32.f32 %0, %1;" : "=r"(u) : "f"(x));
    return u;
}

__device__ __forceinline__ void mma16x8x8(float* c, const uint32_t* a,
                                          const uint32_t* b) {
    asm volatile(
        "mma.sync.aligned.m16n8k8.row.col.f32.tf32.tf32.f32 "
        "{%0,%1,%2,%3}, {%4,%5,%6,%7}, {%8,%9}, {%0,%1,%2,%3};\n"
        : "+f"(c[0]), "+f"(c[1]), "+f"(c[2]), "+f"(c[3])
        : "r"(a[0]), "r"(a[1]), "r"(a[2]), "r"(a[3]), "r"(b[0]), "r"(b[1]));
}

// ---------------------------------------------------------------------------
// TF32 tensor-core GEMM: C[M,N] = A[M,K] @ B[K,N], row-major fp32 in/out.
// 128x128 block tile, BK=16 double-buffered, 256 threads, 64x32 warp tile.
// ---------------------------------------------------------------------------
__global__ __launch_bounds__(256, 2) void tf32_gemm_kernel(
    const float* __restrict__ A, const float* __restrict__ B,
    float* __restrict__ C, int M, int N, int K)
{
    __shared__ uint32_t As[2][128][20];   // [m][k], pad 20 -> conflict-free frags
    __shared__ uint32_t Bs[2][16][136];   // [k][n], pad 136

    const int tid  = threadIdx.x;
    const int lane = tid & 31;
    const int warp = tid >> 5;
    const int wm   = (warp >> 2) * 64;
    const int wn   = (warp & 3) * 32;
    const int grp  = lane >> 2;
    const int qid  = lane & 3;
    const int bm   = blockIdx.y * 128;
    const int bn   = blockIdx.x * 128;

    // gmem load mapping (BK=16): A two rows/thread, B two rows/thread
    const int ar = tid >> 2;             // 0..63
    const int ac = (tid & 3) << 2;       // 0,4,8,12
    const int br = tid >> 5;             // 0..7
    const int bc = (tid & 31) << 2;      // 0..124
    const float* Ap0 = A + (size_t)(bm + ar) * K + ac;
    const float* Ap1 = A + (size_t)(bm + ar + 64) * K + ac;
    const float* Bp0 = B + (size_t)br * N + bn + bc;
    const float* Bp1 = B + (size_t)(br + 8) * N + bn + bc;

    float c[4][4][4];
    #pragma unroll
    for (int mi = 0; mi < 4; mi++)
        #pragma unroll
        for (int ni = 0; ni < 4; ni++)
            #pragma unroll
            for (int r = 0; r < 4; r++) c[mi][ni][r] = 0.f;

    // preload tile 0
    float4 sa0 = *(const float4*)Ap0;
    float4 sa1 = *(const float4*)Ap1;
    float4 sb0 = *(const float4*)Bp0;
    float4 sb1 = *(const float4*)Bp1;
    {
        uint4 u;
        u.x = f2tf(sa0.x); u.y = f2tf(sa0.y); u.z = f2tf(sa0.z); u.w = f2tf(sa0.w);
        *(uint4*)&As[0][ar][ac] = u;
        u.x = f2tf(sa1.x); u.y = f2tf(sa1.y); u.z = f2tf(sa1.z); u.w = f2tf(sa1.w);
        *(uint4*)&As[0][ar + 64][ac] = u;
        u.x = f2tf(sb0.x); u.y = f2tf(sb0.y); u.z = f2tf(sb0.z); u.w = f2tf(sb0.w);
        *(uint4*)&Bs[0][br][bc] = u;
        u.x = f2tf(sb1.x); u.y = f2tf(sb1.y); u.z = f2tf(sb1.z); u.w = f2tf(sb1.w);
        *(uint4*)&Bs[0][br + 8][bc] = u;
    }
    __syncthreads();

    int buf = 0;
    for (int k0 = 16; k0 <= K; k0 += 16) {
        if (k0 < K) {
            sa0 = *(const float4*)(Ap0 + k0);
            sa1 = *(const float4*)(Ap1 + k0);
            sb0 = *(const float4*)(Bp0 + (size_t)k0 * N);
            sb1 = *(const float4*)(Bp1 + (size_t)k0 * N);
        }
        #pragma unroll
        for (int kk = 0; kk < 16; kk += 8) {
            uint32_t a[4][4], b[4][2];
            #pragma unroll
            for (int mi = 0; mi < 4; mi++) {
                const int m = wm + mi * 16 + grp;
                a[mi][0] = As[buf][m][kk + qid];
                a[mi][1] = As[buf][m + 8][kk + qid];
                a[mi][2] = As[buf][m][kk + qid + 4];
                a[mi][3] = As[buf][m + 8][kk + qid + 4];
            }
            #pragma unroll
            for (int ni = 0; ni < 4; ni++) {
                const int n = wn + ni * 8 + grp;
                b[ni][0] = Bs[buf][kk + qid][n];
                b[ni][1] = Bs[buf][kk + qid + 4][n];
            }
            #pragma unroll
            for (int mi = 0; mi < 4; mi++)
                #pragma unroll
                for (int ni = 0; ni < 4; ni++)
                    mma16x8x8(c[mi][ni], a[mi], b[ni]);
        }
        if (k0 < K) {
            const int nb = buf ^ 1;
            uint4 u;
            u.x = f2tf(sa0.x); u.y = f2tf(sa0.y); u.z = f2tf(sa0.z); u.w = f2tf(sa0.w);
            *(uint4*)&As[nb][ar][ac] = u;
            u.x = f2tf(sa1.x); u.y = f2tf(sa1.y); u.z = f2tf(sa1.z); u.w = f2tf(sa1.w);
            *(uint4*)&As[nb][ar + 64][ac] = u;
            u.x = f2tf(sb0.x); u.y = f2tf(sb0.y); u.z = f2tf(sb0.z); u.w = f2tf(sb0.w);
            *(uint4*)&Bs[nb][br][bc] = u;
            u.x = f2tf(sb1.x); u.y = f2tf(sb1.y); u.z = f2tf(sb1.z); u.w = f2tf(sb1.w);
            *(uint4*)&Bs[nb][br + 8][bc] = u;
        }
        __syncthreads();
        buf ^= 1;
    }

    #pragma unroll
    for (int mi = 0; mi < 4; mi++) {
        const int row0 = bm + wm + mi * 16 + grp;
        #pragma unroll
        for (int ni = 0; ni < 4; ni++) {
            const int col = bn + wn + ni * 8 + qid * 2;
            *(float2*)&C[(size_t)row0 * N + col] =
                make_float2(c[mi][ni][0], c[mi][ni][1]);
            *(float2*)&C[(size_t)(row0 + 8) * N + col] =
                make_float2(c[mi][ni][2], c[mi][ni][3]);
        }
    }
}

// ---------------------------------------------------------------------------
// RoPE: in-place on x laid out [B, S, heads, HD].
// ---------------------------------------------------------------------------
__global__ void rope_kernel(float* __restrict__ x,
                            const float* __restrict__ cosT,
                            const float* __restrict__ sinT, int heads)
{
    const int idx  = blockIdx.x * blockDim.x + threadIdx.x;
    const int half = idx & 63;
    const int h    = (idx >> 6) % heads;
    const int s    = (idx / (64 * heads)) % SS;
    const int b    = idx / (64 * heads * SS);

    float* p = x + (size_t)((b * SS + s) * heads + h) * HDD;
    const float x1 = p[half];
    const float x2 = p[half + 64];
    const float c1 = cosT[s * HDD + half];
    const float s1 = sinT[s * HDD + half];
    const float c2 = cosT[s * HDD + half + 64];
    const float s2 = sinT[s * HDD + half + 64];
    p[half]      = x1 * c1 - x2 * s1;
    p[half + 64] = x2 * c2 + x1 * s2;
}

// ---------------------------------------------------------------------------
// Tensor-core flash attention (tf32 mma), causal + alibi + mask.
// Grid (S/64, B*H), 256 threads (8 warps, 4x2).
// Scores: warp tile 16x32.  PV: warp tile 16x64.  Online softmax in fp32.
// ---------------------------------------------------------------------------
struct AttSmem {
    uint32_t Qs[64][132];   // tf32 bits, pre-scaled
    uint32_t Ks[64][132];   // tf32 bits
    uint32_t Vs[64][136];   // tf32 bits
    uint32_t Sc[64][68];    // scores fp32 bits -> P tf32 bits
    float Red[4][64];
    float RedS[4][64];
    float Fac[64];
};

__global__ __launch_bounds__(256) void attn_kernel(
    const float* __restrict__ q, const float* __restrict__ k,
    const float* __restrict__ v, const float* __restrict__ alibi,
    const float* __restrict__ mask, float* __restrict__ ctx)
{
    extern __shared__ char smem_raw[];
    AttSmem& sm = *reinterpret_cast<AttSmem*>(smem_raw);

    const int tid   = threadIdx.x;
    const int lane  = tid & 31;
    const int warp  = tid >> 5;
    const int wr    = warp >> 1;        // 0..3 (16-row band)
    const int wc    = warp & 1;         // 0..1
    const int grp   = lane >> 2;
    const int qid   = lane & 3;
    const int qtile = blockIdx.x;
    const int bh    = blockIdx.y;
    const int b     = bh / HH;
    const int h     = bh % HH;
    const int kh    = h / GG;
    const int q0    = qtile * 64;

    const float scale = 0.08838834764831845f;  // 1/sqrt(128)

    // load Q tile: scaled, tf32-rounded
    #pragma unroll
    for (int i = 0; i < 8; i++) {
        const int idx = tid + i * 256;
        const int r   = idx >> 5;
        const int c4  = (idx & 31) << 2;
        const float4 a = *(const float4*)(q + (size_t)((b * SS + q0 + r) * HH + h) * HDD + c4);
        uint4 u;
        u.x = f2tf(a.x * scale); u.y = f2tf(a.y * scale);
        u.z = f2tf(a.z * scale); u.w = f2tf(a.w * scale);
        *(uint4*)&sm.Qs[r][c4] = u;
    }

    float o[8][4];
    #pragma unroll
    for (int ni = 0; ni < 8; ni++)
        #pragma unroll
        for (int r = 0; r < 4; r++) o[ni][r] = 0.f;

    const int row = tid & 63;   // softmax row ownership
    const int q4  = tid >> 6;   // softmax quarter
    float m_i = -1e30f, l_i = 0.f;

    const int rl = wr * 16 + grp;   // local q row of frag (also rl+8)

    const int ntiles = qtile + 1;
    for (int t = 0; t < ntiles; t++) {
        const int kv0 = t * 64;
        __syncthreads();   // protect Ks/Vs/Sc from previous iteration readers

        // load K,V tiles (tf32)
        #pragma unroll
        for (int i = 0; i < 8; i++) {
            const int idx = tid + i * 256;
            const int r   = idx >> 5;
            const int c4  = (idx & 31) << 2;
            const size_t base = (size_t)((b * SS + kv0 + r) * KVHH + kh) * HDD + c4;
            const float4 kv4 = *(const float4*)(k + base);
            const float4 vv4 = *(const float4*)(v + base);
            uint4 u;
            u.x = f2tf(kv4.x); u.y = f2tf(kv4.y); u.z = f2tf(kv4.z); u.w = f2tf(kv4.w);
            *(uint4*)&sm.Ks[r][c4] = u;
            u.x = f2tf(vv4.x); u.y = f2tf(vv4.y); u.z = f2tf(vv4.z); u.w = f2tf(vv4.w);
            *(uint4*)&sm.Vs[r][c4] = u;
        }
        __syncthreads();

        // ---- scores: S = Q @ K^T (warp tile 16x32) ----
        float sf[4][4];
        #pragma unroll
        for (int ni = 0; ni < 4; ni++)
            #pragma unroll
            for (int r = 0; r < 4; r++) sf[ni][r] = 0.f;

        #pragma unroll
        for (int kk = 0; kk < HDD; kk += 8) {
            uint32_t a[4];
            a[0] = sm.Qs[rl][kk + qid];
            a[1] = sm.Qs[rl + 8][kk + qid];
            a[2] = sm.Qs[rl][kk + qid + 4];
            a[3] = sm.Qs[rl + 8][kk + qid + 4];
            #pragma unroll
            for (int ni = 0; ni < 4; ni++) {
                const int n = wc * 32 + ni * 8 + grp;
                uint32_t bb[2] = { sm.Ks[n][kk + qid], sm.Ks[n][kk + qid + 4] };
                mma16x8x8(sf[ni], a, bb);
            }
        }

        // ---- bias + causal, write scores to Sc ----
        const int rg = q0 + rl;
        const bool diag = (t == qtile);
        #pragma unroll
        for (int ni = 0; ni < 4; ni++) {
            const int cl = wc * 32 + ni * 8 + qid * 2;
            const int cg = kv0 + cl;
            const float2 mk  = *(const float2*)(mask + b * SS + cg);
            const float2 al0 = *(const float2*)(alibi + ((size_t)b * SS + rg) * SS + cg);
            const float2 al1 = *(const float2*)(alibi + ((size_t)b * SS + rg + 8) * SS + cg);
            float s0 = sf[ni][0] + al0.x + mk.x;
            float s1 = sf[ni][1] + al0.y + mk.y;
            float s2 = sf[ni][2] + al1.x + mk.x;
            float s3 = sf[ni][3] + al1.y + mk.y;
            if (diag) {
                if (cg > rg)         s0 = -1e30f;
                if (cg + 1 > rg)     s1 = -1e30f;
                if (cg > rg + 8)     s2 = -1e30f;
                if (cg + 1 > rg + 8) s3 = -1e30f;
            }
            sm.Sc[rl][cl]       = __float_as_uint(s0);
            sm.Sc[rl][cl + 1]   = __float_as_uint(s1);
            sm.Sc[rl + 8][cl]   = __float_as_uint(s2);
            sm.Sc[rl + 8][cl + 1] = __float_as_uint(s3);
        }
        __syncthreads();

        // ---- online softmax (fp32 scalar) ----
        float lm = -1e30f;
        #pragma unroll
        for (int j = 0; j < 16; j++)
            lm = fmaxf(lm, __uint_as_float(sm.Sc[row][q4 * 16 + j]));
        sm.Red[q4][row] = lm;
        __syncthreads();

        const float rowmax = fmaxf(fmaxf(sm.Red[0][row], sm.Red[1][row]),
                                   fmaxf(sm.Red[2][row], sm.Red[3][row]));
        const float newm = fmaxf(m_i, rowmax);
        const float fac  = __expf(m_i - newm);
        float ls = 0.f;
        #pragma unroll
        for (int j = 0; j < 16; j++) {
            const float p = __expf(__uint_as_float(sm.Sc[row][q4 * 16 + j]) - newm);
            ls += p;
            sm.Sc[row][q4 * 16 + j] = f2tf(p);     // P as tf32 for PV mma
        }
        sm.RedS[q4][row] = ls;
        if (q4 == 0) sm.Fac[row] = fac;
        m_i = newm;
        __syncthreads();

        l_i = l_i * fac + sm.RedS[0][row] + sm.RedS[1][row]
                        + sm.RedS[2][row] + sm.RedS[3][row];

        // ---- PV: O = O*fac + P @ V (warp tile 16x64) ----
        const float f0 = sm.Fac[rl];
        const float f1 = sm.Fac[rl + 8];
        #pragma unroll
        for (int ni = 0; ni < 8; ni++) {
            o[ni][0] *= f0; o[ni][1] *= f0;
            o[ni][2] *= f1; o[ni][3] *= f1;
        }
        #pragma unroll
        for (int kk = 0; kk < 64; kk += 8) {
            uint32_t a[4];
            a[0] = sm.Sc[rl][kk + qid];
            a[1] = sm.Sc[rl + 8][kk + qid];
            a[2] = sm.Sc[rl][kk + qid + 4];
            a[3] = sm.Sc[rl + 8][kk + qid + 4];
            #pragma unroll
            for (int ni = 0; ni < 8; ni++) {
                const int n = wc * 64 + ni * 8 + grp;
                uint32_t bb[2] = { sm.Vs[kk + qid][n], sm.Vs[kk + qid + 4][n] };
                mma16x8x8(o[ni], a, bb);
            }
        }
    }

    // publish 1/l and write O
    if (q4 == 0) sm.Fac[row] = 1.f / l_i;
    __syncthreads();
    const float il0 = sm.Fac[rl];
    const float il1 = sm.Fac[rl + 8];
    #pragma unroll
    for (int ni = 0; ni < 8; ni++) {
        const int col = wc * 64 + ni * 8 + qid * 2;
        float* d0 = ctx + (size_t)((b * SS + q0 + rl) * HH + h) * HDD + col;
        float* d1 = ctx + (size_t)((b * SS + q0 + rl + 8) * HH + h) * HDD + col;
        *(float2*)d0 = make_float2(o[ni][0] * il0, o[ni][1] * il0);
        *(float2*)d1 = make_float2(o[ni][2] * il1, o[ni][3] * il1);
    }
}

// ---------------------------------------------------------------------------
// Launch
// ---------------------------------------------------------------------------
extern "C" void kernel_launch(void* const* d_in, const int* in_sizes, int n_in,
                              void* d_out, int out_size)
{
    const float* hs    = (const float*)d_in[0];
    const float* cosT  = (const float*)d_in[1];
    const float* sinT  = (const float*)d_in[2];
    const float* alibi = (const float*)d_in[3];
    const float* mask  = (const float*)d_in[4];
    const float* wq    = (const float*)d_in[5];
    const float* wk    = (const float*)d_in[6];
    const float* wv    = (const float*)d_in[7];
    const float* wo    = (const float*)d_in[8];
    float* out = (float*)d_out;

    float *qb, *kb, *vb, *cb;
    cudaGetSymbolAddress((void**)&qb, g_q);
    cudaGetSymbolAddress((void**)&kb, g_k);
    cudaGetSymbolAddress((void**)&vb, g_v);
    cudaGetSymbolAddress((void**)&cb, g_ctx);

    const int M = BB * SS;  // 4096

    // QKV projections (tf32 tensor cores, double-buffered)
    {
        dim3 gq(DD / 128, M / 128);
        tf32_gemm_kernel<<<gq, 256>>>(hs, wq, qb, M, DD, DD);
        dim3 gkv((KVHH * HDD) / 128, M / 128);
        tf32_gemm_kernel<<<gkv, 256>>>(hs, wk, kb, M, KVHH * HDD, DD);
        tf32_gemm_kernel<<<gkv, 256>>>(hs, wv, vb, M, KVHH * HDD, DD);
    }

    // RoPE on Q and K
    {
        const int tq = BB * SS * HH * 64;
        rope_kernel<<<tq / 256, 256>>>(qb, cosT, sinT, HH);
        const int tk = BB * SS * KVHH * 64;
        rope_kernel<<<tk / 256, 256>>>(kb, cosT, sinT, KVHH);
    }

    // Attention (tf32 tensor cores)
    {
        static_assert(sizeof(AttSmem) <= 220 * 1024, "smem too big");
        cudaFuncSetAttribute(attn_kernel,
                             cudaFuncAttributeMaxDynamicSharedMemorySize,
                             (int)sizeof(AttSmem));
        dim3 ga(SS / 64, BB * HH);
        attn_kernel<<<ga, 256, sizeof(AttSmem)>>>(qb, kb, vb, alibi, mask, cb);
    }

    // Output projection -> d_out
    {
        dim3 go(DD / 128, M / 128);
        tf32_gemm_kernel<<<go, 256>>>(cb, wo, out, M, DD, DD);
    }
}

// round 5
// speedup vs baseline: 3.9867x; 1.1681x over previous
#include <cuda_runtime.h>
#include <cuda_bf16.h>
#include <cstdint>
#include <cstddef>

// Problem constants
#define BB   2
#define SS   2048
#define DD   2048
#define HH   16
#define KVHH 4
#define HDD  128
#define GG   4   // H / KVH

// ---------------------------------------------------------------------------
// Scratch (device globals — no allocations allowed)
// ---------------------------------------------------------------------------
__device__ float g_q[BB * SS * HH * HDD];
__device__ float g_k[BB * SS * KVHH * HDD];
__device__ float g_v[BB * SS * KVHH * HDD];
__device__ float g_ctx[BB * SS * HH * HDD];
__device__ float g_hs_t[BB * SS * DD];
__device__ float g_wq_t[DD * DD];
__device__ float g_wk_t[DD * KVHH * HDD];
__device__ float g_wv_t[DD * KVHH * HDD];
__device__ float g_wo_t[DD * DD];

// ---------------------------------------------------------------------------
// helpers
// ---------------------------------------------------------------------------
__device__ __forceinline__ uint32_t f2tf(float x) {
    uint32_t u;
    asm("cvt.rna.tf32.f32 %0, %1;" : "=r"(u) : "f"(x));
    return u;
}

__device__ __forceinline__ void mma16x8x8(float* c, const uint32_t* a,
                                          const uint32_t* b) {
    asm volatile(
        "mma.sync.aligned.m16n8k8.row.col.f32.tf32.tf32.f32 "
        "{%0,%1,%2,%3}, {%4,%5,%6,%7}, {%8,%9}, {%0,%1,%2,%3};\n"
        : "+f"(c[0]), "+f"(c[1]), "+f"(c[2]), "+f"(c[3])
        : "r"(a[0]), "r"(a[1]), "r"(a[2]), "r"(a[3]), "r"(b[0]), "r"(b[1]));
}

__device__ __forceinline__ void cp16(uint32_t dst, const void* src) {
    asm volatile("cp.async.cg.shared.global [%0], [%1], 16;\n"
                 :: "r"(dst), "l"(src));
}
__device__ __forceinline__ void cp_commit() {
    asm volatile("cp.async.commit_group;\n");
}
template <int N>
__device__ __forceinline__ void cp_wait() {
    asm volatile("cp.async.wait_group %0;\n" :: "n"(N));
}

// ---------------------------------------------------------------------------
// tf32 pre-rounding (elementwise, float4)
// ---------------------------------------------------------------------------
__global__ void round_tf32_kernel(const float4* __restrict__ src,
                                  float4* __restrict__ dst, int n4)
{
    for (int i = blockIdx.x * blockDim.x + threadIdx.x; i < n4;
         i += gridDim.x * blockDim.x) {
        float4 v = src[i];
        v.x = __uint_as_float(f2tf(v.x));
        v.y = __uint_as_float(f2tf(v.y));
        v.z = __uint_as_float(f2tf(v.z));
        v.w = __uint_as_float(f2tf(v.w));
        dst[i] = v;
    }
}

// ---------------------------------------------------------------------------
// TF32 GEMM, cp.async 4-stage pipeline.
// C[M,N] = A[M,K] @ B[K,N]; A,B pre-rounded to tf32 (raw bits copied).
// 128x128 tile, BK=16, 256 threads, warp tile 64x32.
// ---------------------------------------------------------------------------
#define G_ASZ (128 * 20)          // u32 per A stage
#define G_BSZ (16 * 136)          // u32 per B stage
#define G_STAGES 4
#define G_SMEM ((G_STAGES * (G_ASZ + G_BSZ)) * 4)

template <bool ROUND>
__global__ __launch_bounds__(256, 2) void tf32_gemm_kernel(
    const float* __restrict__ A, const float* __restrict__ B,
    float* __restrict__ C, int M, int N, int K)
{
    extern __shared__ uint32_t gsm[];
    uint32_t* Asm = gsm;                          // [4][128][20]
    uint32_t* Bsm = gsm + G_STAGES * G_ASZ;       // [4][16][136]
    const uint32_t sbase = (uint32_t)__cvta_generic_to_shared(gsm);
    const uint32_t aoff  = 0;
    const uint32_t boff  = G_STAGES * G_ASZ * 4;

    const int tid  = threadIdx.x;
    const int lane = tid & 31;
    const int warp = tid >> 5;
    const int wm   = (warp >> 2) * 64;
    const int wn   = (warp & 3) * 32;
    const int grp  = lane >> 2;
    const int qid  = lane & 3;
    const int bm   = blockIdx.y * 128;
    const int bn   = blockIdx.x * 128;

    // cp.async mappings
    const int arA = tid >> 2;            // 0..63? no: chunks below
    (void)arA;

    float c[4][4][4];
    #pragma unroll
    for (int mi = 0; mi < 4; mi++)
        #pragma unroll
        for (int ni = 0; ni < 4; ni++)
            #pragma unroll
            for (int r = 0; r < 4; r++) c[mi][ni][r] = 0.f;

    const int T = K / 16;

    auto issue = [&](int s, int k0) {
        const uint32_t as = sbase + aoff + s * G_ASZ * 4;
        #pragma unroll
        for (int i = 0; i < 2; i++) {
            const int ch = tid + i * 256;        // 0..511
            const int r  = ch >> 2;              // 0..127
            const int cl = (ch & 3) << 2;        // 0,4,8,12
            cp16(as + (r * 20 + cl) * 4, A + (size_t)(bm + r) * K + k0 + cl);
        }
        const uint32_t bs = sbase + boff + s * G_BSZ * 4;
        #pragma unroll
        for (int i = 0; i < 2; i++) {
            const int ch = tid + i * 256;
            const int r  = ch >> 5;              // 0..15
            const int cl = (ch & 31) << 2;       // 0..124
            cp16(bs + (r * 136 + cl) * 4, B + (size_t)(k0 + r) * N + bn + cl);
        }
        cp_commit();
    };

    issue(0, 0);
    issue(1, 16);
    issue(2, 32);

    for (int t = 0; t < T; t++) {
        if (t < T - 2)      cp_wait<2>();
        else if (t == T - 2) cp_wait<1>();
        else                 cp_wait<0>();
        __syncthreads();
        if (t + 3 < T) issue((t + 3) & 3, (t + 3) * 16);

        const uint32_t* As = Asm + (t & 3) * G_ASZ;
        const uint32_t* Bs = Bsm + (t & 3) * G_BSZ;
        #pragma unroll
        for (int kk = 0; kk < 16; kk += 8) {
            uint32_t a[4][4], bf[4][2];
            #pragma unroll
            for (int mi = 0; mi < 4; mi++) {
                const int m = wm + mi * 16 + grp;
                a[mi][0] = As[m * 20 + kk + qid];
                a[mi][1] = As[(m + 8) * 20 + kk + qid];
                a[mi][2] = As[m * 20 + kk + qid + 4];
                a[mi][3] = As[(m + 8) * 20 + kk + qid + 4];
            }
            #pragma unroll
            for (int ni = 0; ni < 4; ni++) {
                const int n = wn + ni * 8 + grp;
                bf[ni][0] = Bs[(kk + qid) * 136 + n];
                bf[ni][1] = Bs[(kk + qid + 4) * 136 + n];
            }
            #pragma unroll
            for (int mi = 0; mi < 4; mi++)
                #pragma unroll
                for (int ni = 0; ni < 4; ni++)
                    mma16x8x8(c[mi][ni], a[mi], bf[ni]);
        }
    }

    #pragma unroll
    for (int mi = 0; mi < 4; mi++) {
        const int row0 = bm + wm + mi * 16 + grp;
        #pragma unroll
        for (int ni = 0; ni < 4; ni++) {
            const int col = bn + wn + ni * 8 + qid * 2;
            float v0 = c[mi][ni][0], v1 = c[mi][ni][1];
            float v2 = c[mi][ni][2], v3 = c[mi][ni][3];
            if (ROUND) {
                v0 = __uint_as_float(f2tf(v0)); v1 = __uint_as_float(f2tf(v1));
                v2 = __uint_as_float(f2tf(v2)); v3 = __uint_as_float(f2tf(v3));
            }
            *(float2*)&C[(size_t)row0 * N + col]       = make_float2(v0, v1);
            *(float2*)&C[(size_t)(row0 + 8) * N + col] = make_float2(v2, v3);
        }
    }
}

// ---------------------------------------------------------------------------
// RoPE: in-place, applies optional scale, rounds result to tf32.
// ---------------------------------------------------------------------------
__global__ void rope_kernel(float* __restrict__ x,
                            const float* __restrict__ cosT,
                            const float* __restrict__ sinT, int heads,
                            float scale)
{
    const int idx  = blockIdx.x * blockDim.x + threadIdx.x;
    const int half = idx & 63;
    const int h    = (idx >> 6) % heads;
    const int s    = (idx / (64 * heads)) % SS;
    const int b    = idx / (64 * heads * SS);

    float* p = x + (size_t)((b * SS + s) * heads + h) * HDD;
    const float x1 = p[half];
    const float x2 = p[half + 64];
    const float c1 = cosT[s * HDD + half];
    const float s1 = sinT[s * HDD + half];
    const float c2 = cosT[s * HDD + half + 64];
    const float s2 = sinT[s * HDD + half + 64];
    p[half]      = __uint_as_float(f2tf((x1 * c1 - x2 * s1) * scale));
    p[half + 64] = __uint_as_float(f2tf((x2 * c2 + x1 * s2) * scale));
}

// ---------------------------------------------------------------------------
// Tensor-core flash attention, BM=128, BN=64, 8 warps (warp owns 16 q rows).
// Warp-local softmax via shuffles. cp.async: Q once; K double-buffered;
// V single-buffered, hidden behind scores+softmax.
// Inputs q (pre-scaled+rounded), k, v (rounded). Output ctx rounded to tf32.
// ---------------------------------------------------------------------------
#define A_QS  (128 * 132)
#define A_KS  (64 * 132)
#define A_VS  (64 * 136)
#define A_SC  (128 * 68)
#define A_SMEM ((A_QS + 2 * A_KS + A_VS + A_SC) * 4)

__global__ __launch_bounds__(256, 1) void attn_kernel(
    const float* __restrict__ q, const float* __restrict__ k,
    const float* __restrict__ v, const float* __restrict__ alibi,
    const float* __restrict__ mask, float* __restrict__ ctx)
{
    extern __shared__ uint32_t attsm[];
    uint32_t* Qs = attsm;                    // [128][132]
    uint32_t* Ks = Qs + A_QS;                // [2][64][132]
    uint32_t* Vs = Ks + 2 * A_KS;            // [64][136]
    uint32_t* Sc = Vs + A_VS;                // [128][68]
    const uint32_t sbase = (uint32_t)__cvta_generic_to_shared(attsm);
    const uint32_t qoff  = 0;
    const uint32_t koff  = A_QS * 4;
    const uint32_t voff  = (A_QS + 2 * A_KS) * 4;

    const int tid  = threadIdx.x;
    const int lane = tid & 31;
    const int warp = tid >> 5;              // 0..7: q-row band
    const int grp  = lane >> 2;
    const int qid  = lane & 3;
    const int bx   = blockIdx.x;
    const int bh   = blockIdx.y;
    const int b    = bh / HH;
    const int h    = bh % HH;
    const int kh   = h / GG;
    const int q0   = bx * 128;
    const int rl   = warp * 16 + grp;       // local row (and rl+8)

    const int ntiles = 2 * bx + 2;

    // prologue: group1 = Q + K[0], group2 = V[0]
    #pragma unroll
    for (int i = 0; i < 16; i++) {
        const int ch = tid + i * 256;
        const int r  = ch >> 5;
        const int cl = (ch & 31) << 2;
        cp16(sbase + qoff + (r * 132 + cl) * 4,
             q + (size_t)((b * SS + q0 + r) * HH + h) * HDD + cl);
    }
    #pragma unroll
    for (int i = 0; i < 8; i++) {
        const int ch = tid + i * 256;
        const int r  = ch >> 5;
        const int cl = (ch & 31) << 2;
        cp16(sbase + koff + (r * 132 + cl) * 4,
             k + (size_t)((b * SS + r) * KVHH + kh) * HDD + cl);
    }
    cp_commit();
    #pragma unroll
    for (int i = 0; i < 8; i++) {
        const int ch = tid + i * 256;
        const int r  = ch >> 5;
        const int cl = (ch & 31) << 2;
        cp16(sbase + voff + (r * 136 + cl) * 4,
             v + (size_t)((b * SS + r) * KVHH + kh) * HDD + cl);
    }
    cp_commit();

    float o[16][4];
    #pragma unroll
    for (int ni = 0; ni < 16; ni++)
        #pragma unroll
        for (int r = 0; r < 4; r++) o[ni][r] = 0.f;
    float m0 = -1e30f, m1 = -1e30f, l0 = 0.f, l1 = 0.f;

    const int rg0 = q0 + rl;
    const int rg1 = rg0 + 8;

    for (int t = 0; t < ntiles; t++) {
        const int kv0 = t * 64;
        const int pk  = t & 1;

        cp_wait<1>();            // K[t] (and Q on t=0) done; V[t] may pend
        __syncthreads();

        if (t + 1 < ntiles) {    // prefetch K[t+1] into other buffer
            const int kv1 = kv0 + 64;
            #pragma unroll
            for (int i = 0; i < 8; i++) {
                const int ch = tid + i * 256;
                const int r  = ch >> 5;
                const int cl = (ch & 31) << 2;
                cp16(sbase + koff + (((t + 1) & 1) * A_KS + r * 132 + cl) * 4,
                     k + (size_t)((b * SS + kv1 + r) * KVHH + kh) * HDD + cl);
            }
            cp_commit();
        }

        // prefetch alibi + mask for this tile (consumed after scores)
        float2 al0[8], al1[8], mk[8];
        #pragma unroll
        for (int ni = 0; ni < 8; ni++) {
            const int cg = kv0 + ni * 8 + 2 * qid;
            mk[ni]  = *(const float2*)(mask + b * SS + cg);
            al0[ni] = *(const float2*)(alibi + ((size_t)b * SS + rg0) * SS + cg);
            al1[ni] = *(const float2*)(alibi + ((size_t)b * SS + rg1) * SS + cg);
        }

        // ---- scores: 16x64 warp tile ----
        float sf[8][4];
        #pragma unroll
        for (int ni = 0; ni < 8; ni++)
            #pragma unroll
            for (int r = 0; r < 4; r++) sf[ni][r] = 0.f;

        const uint32_t* Kb = Ks + pk * A_KS;
        #pragma unroll
        for (int kk = 0; kk < HDD; kk += 8) {
            uint32_t a[4];
            a[0] = Qs[rl * 132 + kk + qid];
            a[1] = Qs[(rl + 8) * 132 + kk + qid];
            a[2] = Qs[rl * 132 + kk + qid + 4];
            a[3] = Qs[(rl + 8) * 132 + kk + qid + 4];
            #pragma unroll
            for (int ni = 0; ni < 8; ni++) {
                const int n = ni * 8 + grp;
                uint32_t bf[2] = { Kb[n * 132 + kk + qid],
                                   Kb[n * 132 + kk + qid + 4] };
                mma16x8x8(sf[ni], a, bf);
            }
        }

        // ---- bias + causal ----
        const bool diag = (t >= 2 * bx);
        #pragma unroll
        for (int ni = 0; ni < 8; ni++) {
            const int cg = kv0 + ni * 8 + 2 * qid;
            sf[ni][0] += al0[ni].x + mk[ni].x;
            sf[ni][1] += al0[ni].y + mk[ni].y;
            sf[ni][2] += al1[ni].x + mk[ni].x;
            sf[ni][3] += al1[ni].y + mk[ni].y;
            if (diag) {
                if (cg > rg0)     sf[ni][0] = -1e30f;
                if (cg + 1 > rg0) sf[ni][1] = -1e30f;
                if (cg > rg1)     sf[ni][2] = -1e30f;
                if (cg + 1 > rg1) sf[ni][3] = -1e30f;
            }
        }

        // ---- warp-local online softmax (rows rg0, rg1) ----
        float mx0 = -1e30f, mx1 = -1e30f;
        #pragma unroll
        for (int ni = 0; ni < 8; ni++) {
            mx0 = fmaxf(mx0, fmaxf(sf[ni][0], sf[ni][1]));
            mx1 = fmaxf(mx1, fmaxf(sf[ni][2], sf[ni][3]));
        }
        mx0 = fmaxf(mx0, __shfl_xor_sync(0xffffffffu, mx0, 1));
        mx0 = fmaxf(mx0, __shfl_xor_sync(0xffffffffu, mx0, 2));
        mx1 = fmaxf(mx1, __shfl_xor_sync(0xffffffffu, mx1, 1));
        mx1 = fmaxf(mx1, __shfl_xor_sync(0xffffffffu, mx1, 2));

        const float nm0 = fmaxf(m0, mx0);
        const float nm1 = fmaxf(m1, mx1);
        const float f0  = __expf(m0 - nm0);
        const float f1  = __expf(m1 - nm1);
        float ls0 = 0.f, ls1 = 0.f;
        #pragma unroll
        for (int ni = 0; ni < 8; ni++) {
            float p0 = __expf(sf[ni][0] - nm0);
            float p1 = __expf(sf[ni][1] - nm0);
            float p2 = __expf(sf[ni][2] - nm1);
            float p3 = __expf(sf[ni][3] - nm1);
            ls0 += p0 + p1;
            ls1 += p2 + p3;
            const int cl = ni * 8 + 2 * qid;
            *(uint2*)&Sc[rl * 68 + cl]       = make_uint2(f2tf(p0), f2tf(p1));
            *(uint2*)&Sc[(rl + 8) * 68 + cl] = make_uint2(f2tf(p2), f2tf(p3));
        }
        ls0 += __shfl_xor_sync(0xffffffffu, ls0, 1);
        ls0 += __shfl_xor_sync(0xffffffffu, ls0, 2);
        ls1 += __shfl_xor_sync(0xffffffffu, ls1, 1);
        ls1 += __shfl_xor_sync(0xffffffffu, ls1, 2);
        l0 = l0 * f0 + ls0;  m0 = nm0;
        l1 = l1 * f1 + ls1;  m1 = nm1;

        #pragma unroll
        for (int ni = 0; ni < 16; ni++) {
            o[ni][0] *= f0; o[ni][1] *= f0;
            o[ni][2] *= f1; o[ni][3] *= f1;
        }
        __syncwarp();            // P visible within warp

        // V[t] complete + visible to all threads
        if (t + 1 < ntiles) cp_wait<1>();
        else                cp_wait<0>();
        __syncthreads();

        // ---- PV: 16x128 warp tile ----
        #pragma unroll
        for (int kk = 0; kk < 64; kk += 8) {
            uint32_t a[4];
            a[0] = Sc[rl * 68 + kk + qid];
            a[1] = Sc[(rl + 8) * 68 + kk + qid];
            a[2] = Sc[rl * 68 + kk + qid + 4];
            a[3] = Sc[(rl + 8) * 68 + kk + qid + 4];
            #pragma unroll
            for (int ni = 0; ni < 16; ni++) {
                const int n = ni * 8 + grp;
                uint32_t bf[2] = { Vs[(kk + qid) * 136 + n],
                                   Vs[(kk + qid + 4) * 136 + n] };
                mma16x8x8(o[ni], a, bf);
            }
        }
        __syncthreads();         // all warps done reading Vs

        if (t + 1 < ntiles) {    // prefetch V[t+1]
            const int kv1 = kv0 + 64;
            #pragma unroll
            for (int i = 0; i < 8; i++) {
                const int ch = tid + i * 256;
                const int r  = ch >> 5;
                const int cl = (ch & 31) << 2;
                cp16(sbase + voff + (r * 136 + cl) * 4,
                     v + (size_t)((b * SS + kv1 + r) * KVHH + kh) * HDD + cl);
            }
            cp_commit();
        }
    }

    // epilogue: normalize, round to tf32 (feeds out-proj), write
    const float il0 = 1.f / l0;
    const float il1 = 1.f / l1;
    #pragma unroll
    for (int ni = 0; ni < 16; ni++) {
        const int col = ni * 8 + 2 * qid;
        float* d0 = ctx + (size_t)((b * SS + rg0) * HH + h) * HDD + col;
        float* d1 = ctx + (size_t)((b * SS + rg1) * HH + h) * HDD + col;
        *(float2*)d0 = make_float2(__uint_as_float(f2tf(o[ni][0] * il0)),
                                   __uint_as_float(f2tf(o[ni][1] * il0)));
        *(float2*)d1 = make_float2(__uint_as_float(f2tf(o[ni][2] * il1)),
                                   __uint_as_float(f2tf(o[ni][3] * il1)));
    }
}

// ---------------------------------------------------------------------------
// Launch
// ---------------------------------------------------------------------------
extern "C" void kernel_launch(void* const* d_in, const int* in_sizes, int n_in,
                              void* d_out, int out_size)
{
    const float* hs    = (const float*)d_in[0];
    const float* cosT  = (const float*)d_in[1];
    const float* sinT  = (const float*)d_in[2];
    const float* alibi = (const float*)d_in[3];
    const float* mask  = (const float*)d_in[4];
    const float* wq    = (const float*)d_in[5];
    const float* wk    = (const float*)d_in[6];
    const float* wv    = (const float*)d_in[7];
    const float* wo    = (const float*)d_in[8];
    float* out = (float*)d_out;

    float *qb, *kb, *vb, *cb, *hst, *wqt, *wkt, *wvt, *wot;
    cudaGetSymbolAddress((void**)&qb,  g_q);
    cudaGetSymbolAddress((void**)&kb,  g_k);
    cudaGetSymbolAddress((void**)&vb,  g_v);
    cudaGetSymbolAddress((void**)&cb,  g_ctx);
    cudaGetSymbolAddress((void**)&hst, g_hs_t);
    cudaGetSymbolAddress((void**)&wqt, g_wq_t);
    cudaGetSymbolAddress((void**)&wkt, g_wk_t);
    cudaGetSymbolAddress((void**)&wvt, g_wv_t);
    cudaGetSymbolAddress((void**)&wot, g_wo_t);

    const int M = BB * SS;   // 4096
    const int NKV = KVHH * HDD;  // 512

    // pre-round inputs to tf32
    round_tf32_kernel<<<1024, 256>>>((const float4*)hs, (float4*)hst,
                                     BB * SS * DD / 4);
    round_tf32_kernel<<<1024, 256>>>((const float4*)wq, (float4*)wqt,
                                     DD * DD / 4);
    round_tf32_kernel<<<256, 256>>>((const float4*)wk, (float4*)wkt,
                                    DD * NKV / 4);
    round_tf32_kernel<<<256, 256>>>((const float4*)wv, (float4*)wvt,
                                    DD * NKV / 4);
    round_tf32_kernel<<<1024, 256>>>((const float4*)wo, (float4*)wot,
                                     DD * DD / 4);

    cudaFuncSetAttribute(tf32_gemm_kernel<false>,
                         cudaFuncAttributeMaxDynamicSharedMemorySize, G_SMEM);
    cudaFuncSetAttribute(tf32_gemm_kernel<true>,
                         cudaFuncAttributeMaxDynamicSharedMemorySize, G_SMEM);

    // QKV projections
    {
        dim3 gq(DD / 128, M / 128);
        tf32_gemm_kernel<false><<<gq, 256, G_SMEM>>>(hst, wqt, qb, M, DD, DD);
        dim3 gkv(NKV / 128, M / 128);
        tf32_gemm_kernel<false><<<gkv, 256, G_SMEM>>>(hst, wkt, kb, M, NKV, DD);
        tf32_gemm_kernel<true><<<gkv, 256, G_SMEM>>>(hst, wvt, vb, M, NKV, DD);
    }

    // RoPE (rounds to tf32; Q pre-scaled by 1/sqrt(HD))
    {
        const float scale = 0.08838834764831845f;
        const int tq = BB * SS * HH * 64;
        rope_kernel<<<tq / 256, 256>>>(qb, cosT, sinT, HH, scale);
        const int tk = BB * SS * KVHH * 64;
        rope_kernel<<<tk / 256, 256>>>(kb, cosT, sinT, KVHH, 1.0f);
    }

    // Attention
    {
        cudaFuncSetAttribute(attn_kernel,
                             cudaFuncAttributeMaxDynamicSharedMemorySize,
                             A_SMEM);
        dim3 ga(SS / 128, BB * HH);   // 16 x 32
        attn_kernel<<<ga, 256, A_SMEM>>>(qb, kb, vb, alibi, mask, cb);
    }

    // Output projection -> d_out
    {
        dim3 go(DD / 128, M / 128);
        tf32_gemm_kernel<false><<<go, 256, G_SMEM>>>(cb, wot, out, M, DD, DD);
    }
}

// round 7
// speedup vs baseline: 6.3837x; 1.6013x over previous
#include <cuda_runtime.h>
#include <cuda_fp16.h>
#include <cstdint>
#include <cstddef>

// Problem constants
#define BB   2
#define SS   2048
#define DD   2048
#define HH   16
#define KVHH 4
#define HDD  128
#define GG   4   // H / KVH

// ---------------------------------------------------------------------------
// Scratch (device globals — no allocations allowed)
// ---------------------------------------------------------------------------
__device__ float  g_q[BB * SS * HH * HDD];        // fp32 GEMM out
__device__ float  g_k[BB * SS * KVHH * HDD];
__device__ float  g_v[BB * SS * KVHH * HDD];
__device__ __half g_qh[BB * SS * HH * HDD];       // post-rope fp16
__device__ __half g_kh[BB * SS * KVHH * HDD];
__device__ __half g_vt[BB * KVHH * HDD * SS];     // V^T per head: [b][kh][hd][s]
__device__ __half g_ctx[BB * SS * HH * HDD];
__device__ __half g_hs_h[BB * SS * DD];
__device__ __half g_wq_h[DD * DD];                // transposed [N][K]
__device__ __half g_wk_h[KVHH * HDD * DD];
__device__ __half g_wv_h[KVHH * HDD * DD];
__device__ __half g_wo_h[DD * DD];

// ---------------------------------------------------------------------------
// helpers
// ---------------------------------------------------------------------------
__device__ __forceinline__ void mma16x8x16(float* c, const uint32_t* a,
                                           const uint32_t* b) {
    asm volatile(
        "mma.sync.aligned.m16n8k16.row.col.f32.f16.f16.f32 "
        "{%0,%1,%2,%3}, {%4,%5,%6,%7}, {%8,%9}, {%0,%1,%2,%3};\n"
        : "+f"(c[0]), "+f"(c[1]), "+f"(c[2]), "+f"(c[3])
        : "r"(a[0]), "r"(a[1]), "r"(a[2]), "r"(a[3]), "r"(b[0]), "r"(b[1]));
}

__device__ __forceinline__ void cp16(uint32_t dst, const void* src) {
    asm volatile("cp.async.cg.shared.global [%0], [%1], 16;\n"
                 :: "r"(dst), "l"(src));
}
__device__ __forceinline__ void cp_commit() {
    asm volatile("cp.async.commit_group;\n");
}
template <int N>
__device__ __forceinline__ void cp_wait() {
    asm volatile("cp.async.wait_group %0;\n" :: "n"(N));
}

// ---------------------------------------------------------------------------
// pre-processing kernels
// ---------------------------------------------------------------------------
__global__ void f2h_kernel(const float4* __restrict__ src,
                           uint2* __restrict__ dst, int n4)
{
    for (int i = blockIdx.x * blockDim.x + threadIdx.x; i < n4;
         i += gridDim.x * blockDim.x) {
        const float4 v = src[i];
        const __half2 lo = __floats2half2_rn(v.x, v.y);
        const __half2 hi = __floats2half2_rn(v.z, v.w);
        uint2 u;
        u.x = *(const uint32_t*)&lo;
        u.y = *(const uint32_t*)&hi;
        dst[i] = u;
    }
}

// dst_h[C][R] = (half)src[R][C]; grid (C/32, R/32), block (32,8)
__global__ void transpose_h_kernel(const float* __restrict__ src,
                                   __half* __restrict__ dst, int R, int C)
{
    __shared__ float t[32][33];
    const int c0 = blockIdx.x * 32;
    const int r0 = blockIdx.y * 32;
    const int tx = threadIdx.x, ty = threadIdx.y;
    #pragma unroll
    for (int i = 0; i < 4; i++)
        t[ty + 8 * i][tx] = src[(size_t)(r0 + ty + 8 * i) * C + c0 + tx];
    __syncthreads();
    #pragma unroll
    for (int i = 0; i < 4; i++)
        dst[(size_t)(c0 + ty + 8 * i) * R + r0 + tx] =
            __float2half(t[tx][ty + 8 * i]);
}

// V [b][s][kvh][hd] fp32 -> Vt [b][kvh][hd][s] fp16
// grid (HDD/32, SS/32, BB*KVHH), block (32,8)
__global__ void vtrans_kernel(const float* __restrict__ v,
                              __half* __restrict__ vt)
{
    __shared__ float t[32][33];
    const int hd0 = blockIdx.x * 32;
    const int s0  = blockIdx.y * 32;
    const int bk  = blockIdx.z;
    const int b   = bk / KVHH;
    const int kh  = bk % KVHH;
    const int tx = threadIdx.x, ty = threadIdx.y;
    #pragma unroll
    for (int i = 0; i < 4; i++)
        t[ty + 8 * i][tx] =
            v[(size_t)((b * SS + s0 + ty + 8 * i) * KVHH + kh) * HDD + hd0 + tx];
    __syncthreads();
    #pragma unroll
    for (int i = 0; i < 4; i++)
        vt[((size_t)(b * KVHH + kh) * HDD + hd0 + ty + 8 * i) * SS + s0 + tx] =
            __float2half(t[tx][ty + 8 * i]);
}

// ---------------------------------------------------------------------------
// FP16 tensor-core GEMM: C[M,N](fp32) = Ah[M,K] @ Bth[N,K]^T.
// 128x128 tile, BK=32, 4-stage cp.async, 256 threads, warp tile 64x32.
// smem strides 40 halfs (pad 8) -> conflict-free half2 frag loads.
// ---------------------------------------------------------------------------
#define HG_STG   20480                      // bytes per stage (A 10240 + B 10240)
#define HG_SMEM  (4 * HG_STG)               // 81920

__global__ __launch_bounds__(256, 2) void hgemm_kernel(
    const __half* __restrict__ A, const __half* __restrict__ Bt,
    float* __restrict__ C, int M, int N, int K)
{
    extern __shared__ char gsm[];
    uint32_t sbase;
    asm("{ .reg .u64 t; cvta.to.shared.u64 t, %1; cvt.u32.u64 %0, t; }"
        : "=r"(sbase) : "l"(gsm));

    const int tid  = threadIdx.x;
    const int lane = tid & 31;
    const int warp = tid >> 5;
    const int wm   = (warp >> 2) * 64;
    const int wn   = (warp & 3) * 32;
    const int grp  = lane >> 2;
    const int qid  = lane & 3;
    const int bm   = blockIdx.y * 128;
    const int bn   = blockIdx.x * 128;

    float c[4][4][4];
    #pragma unroll
    for (int mi = 0; mi < 4; mi++)
        #pragma unroll
        for (int ni = 0; ni < 4; ni++)
            #pragma unroll
            for (int r = 0; r < 4; r++) c[mi][ni][r] = 0.f;

    const int T = K / 32;

    auto issue = [&](int st) {
        const int s = st & 3;
        const uint32_t as = sbase + s * HG_STG;
        const uint32_t bs = as + 10240;
        const int k0 = st * 32;
        #pragma unroll
        for (int i = 0; i < 2; i++) {
            const int ch = tid + i * 256;     // 0..511
            const int r  = ch >> 2;           // 0..127
            const int c8 = (ch & 3) << 3;     // 0,8,16,24 halfs
            cp16(as + (r * 40 + c8) * 2, A + (size_t)(bm + r) * K + k0 + c8);
        }
        #pragma unroll
        for (int i = 0; i < 2; i++) {
            const int ch = tid + i * 256;
            const int r  = ch >> 2;
            const int c8 = (ch & 3) << 3;
            cp16(bs + (r * 40 + c8) * 2, Bt + (size_t)(bn + r) * K + k0 + c8);
        }
        cp_commit();
    };

    issue(0);
    issue(1);
    issue(2);

    for (int t = 0; t < T; t++) {
        if (t < T - 2)       cp_wait<2>();
        else if (t == T - 2) cp_wait<1>();
        else                 cp_wait<0>();
        __syncthreads();
        if (t + 3 < T) issue(t + 3);

        const uint32_t* As32 = (const uint32_t*)(gsm + (t & 3) * HG_STG);
        const uint32_t* Bs32 = (const uint32_t*)(gsm + (t & 3) * HG_STG + 10240);
        #pragma unroll
        for (int kk2 = 0; kk2 < 16; kk2 += 8) {   // two k16 steps (32-bit units)
            uint32_t a[4][4], bf[4][2];
            #pragma unroll
            for (int mi = 0; mi < 4; mi++) {
                const int m = wm + mi * 16 + grp;
                a[mi][0] = As32[m * 20 + kk2 + qid];
                a[mi][1] = As32[(m + 8) * 20 + kk2 + qid];
                a[mi][2] = As32[m * 20 + kk2 + qid + 4];
                a[mi][3] = As32[(m + 8) * 20 + kk2 + qid + 4];
            }
            #pragma unroll
            for (int ni = 0; ni < 4; ni++) {
                const int n = wn + ni * 8 + grp;
                bf[ni][0] = Bs32[n * 20 + kk2 + qid];
                bf[ni][1] = Bs32[n * 20 + kk2 + qid + 4];
            }
            #pragma unroll
            for (int mi = 0; mi < 4; mi++)
                #pragma unroll
                for (int ni = 0; ni < 4; ni++)
                    mma16x8x16(c[mi][ni], a[mi], bf[ni]);
        }
        __syncthreads();
    }

    #pragma unroll
    for (int mi = 0; mi < 4; mi++) {
        const int row0 = bm + wm + mi * 16 + grp;
        #pragma unroll
        for (int ni = 0; ni < 4; ni++) {
            const int col = bn + wn + ni * 8 + qid * 2;
            *(float2*)&C[(size_t)row0 * N + col] =
                make_float2(c[mi][ni][0], c[mi][ni][1]);
            *(float2*)&C[(size_t)(row0 + 8) * N + col] =
                make_float2(c[mi][ni][2], c[mi][ni][3]);
        }
    }
}

// ---------------------------------------------------------------------------
// RoPE: fp32 in -> fp16 out (optional scale folded in).
// ---------------------------------------------------------------------------
__global__ void rope_h_kernel(const float* __restrict__ x,
                              __half* __restrict__ y,
                              const float* __restrict__ cosT,
                              const float* __restrict__ sinT, int heads,
                              float scale)
{
    const int idx  = blockIdx.x * blockDim.x + threadIdx.x;
    const int half = idx & 63;
    const int h    = (idx >> 6) % heads;
    const int s    = (idx / (64 * heads)) % SS;
    const int b    = idx / (64 * heads * SS);

    const size_t base = (size_t)((b * SS + s) * heads + h) * HDD;
    const float x1 = x[base + half];
    const float x2 = x[base + half + 64];
    const float c1 = cosT[s * HDD + half];
    const float s1 = sinT[s * HDD + half];
    const float c2 = cosT[s * HDD + half + 64];
    const float s2 = sinT[s * HDD + half + 64];
    y[base + half]      = __float2half((x1 * c1 - x2 * s1) * scale);
    y[base + half + 64] = __float2half((x2 * c2 + x1 * s2) * scale);
}

// ---------------------------------------------------------------------------
// FP16 tensor-core flash attention. BM=128, BN=64, 8 warps (16 q rows each).
// Q [128][136]h, K 2x[64][136]h, Vt [128][72]h (V^T), Sc/P [128][72]h.
// Warp-local softmax. cp.async pipelined (K double-buffered, Vt behind scores).
// ---------------------------------------------------------------------------
#define AQ_OFF   0
#define AK_OFF   34816                      // 128*136*2
#define AK_STG   17408                      // 64*136*2
#define AV_OFF   69632
#define ASC_OFF  88064                      // AV_OFF + 128*72*2
#define A_SMEM   106496                     // ASC_OFF + 18432

__global__ __launch_bounds__(256, 1) void attn_kernel(
    const __half* __restrict__ q, const __half* __restrict__ k,
    const __half* __restrict__ vt, const float* __restrict__ alibi,
    const float* __restrict__ mask, __half* __restrict__ ctx)
{
    extern __shared__ char asm_raw[];
    uint32_t* S32 = (uint32_t*)asm_raw;
    uint32_t sbase;
    asm("{ .reg .u64 t; cvta.to.shared.u64 t, %1; cvt.u32.u64 %0, t; }"
        : "=r"(sbase) : "l"(asm_raw));

    uint32_t* Q32  = S32;                   // stride 68 (32-bit units)
    uint32_t* K32  = S32 + AK_OFF / 4;      // 2 stages, stride 68
    uint32_t* Vt32 = S32 + AV_OFF / 4;      // stride 36
    uint32_t* Sc32 = S32 + ASC_OFF / 4;     // stride 36

    const int tid  = threadIdx.x;
    const int lane = tid & 31;
    const int warp = tid >> 5;
    const int grp  = lane >> 2;
    const int qid  = lane & 3;
    const int bx   = blockIdx.x;
    const int bh   = blockIdx.y;
    const int b    = bh / HH;
    const int h    = bh % HH;
    const int kh   = h / GG;
    const int q0   = bx * 128;
    const int rl   = warp * 16 + grp;

    const int ntiles = 2 * bx + 2;

    // prologue: group1 = Q + K[0], group2 = Vt[0]
    #pragma unroll
    for (int i = 0; i < 8; i++) {
        const int ch = tid + i * 256;       // 0..2047
        const int r  = ch >> 4;             // 0..127
        const int c8 = (ch & 15) << 3;      // halfs 0..120
        cp16(sbase + AQ_OFF + (r * 136 + c8) * 2,
             q + (size_t)((b * SS + q0 + r) * HH + h) * HDD + c8);
    }
    #pragma unroll
    for (int i = 0; i < 4; i++) {
        const int ch = tid + i * 256;       // 0..1023
        const int r  = ch >> 4;             // 0..63
        const int c8 = (ch & 15) << 3;
        cp16(sbase + AK_OFF + (r * 136 + c8) * 2,
             k + (size_t)((b * SS + r) * KVHH + kh) * HDD + c8);
    }
    cp_commit();
    #pragma unroll
    for (int i = 0; i < 4; i++) {
        const int ch = tid + i * 256;
        const int r  = ch >> 3;             // 0..127 (hd)
        const int c8 = (ch & 7) << 3;       // halfs 0..56 (kv)
        cp16(sbase + AV_OFF + (r * 72 + c8) * 2,
             vt + ((size_t)(b * KVHH + kh) * HDD + r) * SS + c8);
    }
    cp_commit();

    float o[16][4];
    #pragma unroll
    for (int ni = 0; ni < 16; ni++)
        #pragma unroll
        for (int r = 0; r < 4; r++) o[ni][r] = 0.f;
    float m0 = -1e30f, m1 = -1e30f, l0 = 0.f, l1 = 0.f;

    const int rg0 = q0 + rl;
    const int rg1 = rg0 + 8;

    for (int t = 0; t < ntiles; t++) {
        const int kv0 = t * 64;
        const int pk  = t & 1;

        cp_wait<1>();               // K[t] (and Q on t=0) ready; Vt[t] may pend
        __syncthreads();

        if (t + 1 < ntiles) {       // prefetch K[t+1]
            const int kv1 = kv0 + 64;
            #pragma unroll
            for (int i = 0; i < 4; i++) {
                const int ch = tid + i * 256;
                const int r  = ch >> 4;
                const int c8 = (ch & 15) << 3;
                cp16(sbase + AK_OFF + ((t + 1) & 1) * AK_STG + (r * 136 + c8) * 2,
                     k + (size_t)((b * SS + kv1 + r) * KVHH + kh) * HDD + c8);
            }
            cp_commit();
        }

        // prefetch alibi + mask
        float2 al0[8], al1[8], mk[8];
        #pragma unroll
        for (int ni = 0; ni < 8; ni++) {
            const int cg = kv0 + ni * 8 + 2 * qid;
            mk[ni]  = *(const float2*)(mask + b * SS + cg);
            al0[ni] = *(const float2*)(alibi + ((size_t)b * SS + rg0) * SS + cg);
            al1[ni] = *(const float2*)(alibi + ((size_t)b * SS + rg1) * SS + cg);
        }

        // ---- scores: 16x64 warp tile, k16 steps ----
        float sf[8][4];
        #pragma unroll
        for (int ni = 0; ni < 8; ni++)
            #pragma unroll
            for (int r = 0; r < 4; r++) sf[ni][r] = 0.f;

        const uint32_t* Kb = K32 + pk * (AK_STG / 4);
        #pragma unroll
        for (int kk2 = 0; kk2 < 64; kk2 += 8) {     // 32-bit units: HD/2
            uint32_t a[4];
            a[0] = Q32[rl * 68 + kk2 + qid];
            a[1] = Q32[(rl + 8) * 68 + kk2 + qid];
            a[2] = Q32[rl * 68 + kk2 + qid + 4];
            a[3] = Q32[(rl + 8) * 68 + kk2 + qid + 4];
            #pragma unroll
            for (int ni = 0; ni < 8; ni++) {
                const int n = ni * 8 + grp;
                uint32_t bf[2] = { Kb[n * 68 + kk2 + qid],
                                   Kb[n * 68 + kk2 + qid + 4] };
                mma16x8x16(sf[ni], a, bf);
            }
        }

        // ---- bias + causal ----
        const bool diag = (t >= 2 * bx);
        #pragma unroll
        for (int ni = 0; ni < 8; ni++) {
            const int cg = kv0 + ni * 8 + 2 * qid;
            sf[ni][0] += al0[ni].x + mk[ni].x;
            sf[ni][1] += al0[ni].y + mk[ni].y;
            sf[ni][2] += al1[ni].x + mk[ni].x;
            sf[ni][3] += al1[ni].y + mk[ni].y;
            if (diag) {
                if (cg > rg0)     sf[ni][0] = -1e30f;
                if (cg + 1 > rg0) sf[ni][1] = -1e30f;
                if (cg > rg1)     sf[ni][2] = -1e30f;
                if (cg + 1 > rg1) sf[ni][3] = -1e30f;
            }
        }

        // ---- warp-local online softmax ----
        float mx0 = -1e30f, mx1 = -1e30f;
        #pragma unroll
        for (int ni = 0; ni < 8; ni++) {
            mx0 = fmaxf(mx0, fmaxf(sf[ni][0], sf[ni][1]));
            mx1 = fmaxf(mx1, fmaxf(sf[ni][2], sf[ni][3]));
        }
        mx0 = fmaxf(mx0, __shfl_xor_sync(0xffffffffu, mx0, 1));
        mx0 = fmaxf(mx0, __shfl_xor_sync(0xffffffffu, mx0, 2));
        mx1 = fmaxf(mx1, __shfl_xor_sync(0xffffffffu, mx1, 1));
        mx1 = fmaxf(mx1, __shfl_xor_sync(0xffffffffu, mx1, 2));

        const float nm0 = fmaxf(m0, mx0);
        const float nm1 = fmaxf(m1, mx1);
        const float f0  = __expf(m0 - nm0);
        const float f1  = __expf(m1 - nm1);
        float ls0 = 0.f, ls1 = 0.f;
        #pragma unroll
        for (int ni = 0; ni < 8; ni++) {
            const float p0 = __expf(sf[ni][0] - nm0);
            const float p1 = __expf(sf[ni][1] - nm0);
            const float p2 = __expf(sf[ni][2] - nm1);
            const float p3 = __expf(sf[ni][3] - nm1);
            ls0 += p0 + p1;
            ls1 += p2 + p3;
            const __half2 hp0 = __floats2half2_rn(p0, p1);
            const __half2 hp1 = __floats2half2_rn(p2, p3);
            Sc32[rl * 36 + ni * 4 + qid]       = *(const uint32_t*)&hp0;
            Sc32[(rl + 8) * 36 + ni * 4 + qid] = *(const uint32_t*)&hp1;
        }
        ls0 += __shfl_xor_sync(0xffffffffu, ls0, 1);
        ls0 += __shfl_xor_sync(0xffffffffu, ls0, 2);
        ls1 += __shfl_xor_sync(0xffffffffu, ls1, 1);
        ls1 += __shfl_xor_sync(0xffffffffu, ls1, 2);
        l0 = l0 * f0 + ls0;  m0 = nm0;
        l1 = l1 * f1 + ls1;  m1 = nm1;

        #pragma unroll
        for (int ni = 0; ni < 16; ni++) {
            o[ni][0] *= f0; o[ni][1] *= f0;
            o[ni][2] *= f1; o[ni][3] *= f1;
        }
        __syncwarp();               // P (warp-private rows) visible

        // Vt[t] complete + visible
        if (t + 1 < ntiles) cp_wait<1>();
        else                cp_wait<0>();
        __syncthreads();

        // ---- PV: 16x128 warp tile, k16 steps over kv ----
        #pragma unroll
        for (int kk2 = 0; kk2 < 32; kk2 += 8) {     // kv 64 halfs = 32 u32
            uint32_t a[4];
            a[0] = Sc32[rl * 36 + kk2 + qid];
            a[1] = Sc32[(rl + 8) * 36 + kk2 + qid];
            a[2] = Sc32[rl * 36 + kk2 + qid + 4];
            a[3] = Sc32[(rl + 8) * 36 + kk2 + qid + 4];
            #pragma unroll
            for (int ni = 0; ni < 16; ni++) {
                const int n = ni * 8 + grp;         // hd row of Vt
                uint32_t bf[2] = { Vt32[n * 36 + kk2 + qid],
                                   Vt32[n * 36 + kk2 + qid + 4] };
                mma16x8x16(o[ni], a, bf);
            }
        }
        __syncthreads();            // all warps done reading Vt

        if (t + 1 < ntiles) {       // prefetch Vt[t+1]
            const int kv1 = kv0 + 64;
            #pragma unroll
            for (int i = 0; i < 4; i++) {
                const int ch = tid + i * 256;
                const int r  = ch >> 3;
                const int c8 = (ch & 7) << 3;
                cp16(sbase + AV_OFF + (r * 72 + c8) * 2,
                     vt + ((size_t)(b * KVHH + kh) * HDD + r) * SS + kv1 + c8);
            }
            cp_commit();
        }
    }

    // epilogue: normalize, write fp16 ctx
    const float il0 = 1.f / l0;
    const float il1 = 1.f / l1;
    #pragma unroll
    for (int ni = 0; ni < 16; ni++) {
        const int col = ni * 8 + 2 * qid;
        __half* d0 = ctx + (size_t)((b * SS + rg0) * HH + h) * HDD + col;
        __half* d1 = ctx + (size_t)((b * SS + rg1) * HH + h) * HDD + col;
        const __half2 h0 = __floats2half2_rn(o[ni][0] * il0, o[ni][1] * il0);
        const __half2 h1 = __floats2half2_rn(o[ni][2] * il1, o[ni][3] * il1);
        *(__half2*)d0 = h0;
        *(__half2*)d1 = h1;
    }
}

// ---------------------------------------------------------------------------
// Launch
// ---------------------------------------------------------------------------
extern "C" void kernel_launch(void* const* d_in, const int* in_sizes, int n_in,
                              void* d_out, int out_size)
{
    const float* hs    = (const float*)d_in[0];
    const float* cosT  = (const float*)d_in[1];
    const float* sinT  = (const float*)d_in[2];
    const float* alibi = (const float*)d_in[3];
    const float* mask  = (const float*)d_in[4];
    const float* wq    = (const float*)d_in[5];
    const float* wk    = (const float*)d_in[6];
    const float* wv    = (const float*)d_in[7];
    const float* wo    = (const float*)d_in[8];
    float* out = (float*)d_out;

    float  *qb, *kb, *vb;
    __half *qh, *kh, *vt, *cb, *hsh, *wqh, *wkh, *wvh, *woh;
    cudaGetSymbolAddress((void**)&qb,  g_q);
    cudaGetSymbolAddress((void**)&kb,  g_k);
    cudaGetSymbolAddress((void**)&vb,  g_v);
    cudaGetSymbolAddress((void**)&qh,  g_qh);
    cudaGetSymbolAddress((void**)&kh,  g_kh);
    cudaGetSymbolAddress((void**)&vt,  g_vt);
    cudaGetSymbolAddress((void**)&cb,  g_ctx);
    cudaGetSymbolAddress((void**)&hsh, g_hs_h);
    cudaGetSymbolAddress((void**)&wqh, g_wq_h);
    cudaGetSymbolAddress((void**)&wkh, g_wk_h);
    cudaGetSymbolAddress((void**)&wvh, g_wv_h);
    cudaGetSymbolAddress((void**)&woh, g_wo_h);

    const int M   = BB * SS;     // 4096
    const int NKV = KVHH * HDD;  // 512

    // fp16 conversion / weight transposes
    f2h_kernel<<<1024, 256>>>((const float4*)hs, (uint2*)hsh, BB * SS * DD / 4);
    {
        dim3 blk(32, 8);
        transpose_h_kernel<<<dim3(DD / 32, DD / 32), blk>>>(wq, wqh, DD, DD);
        transpose_h_kernel<<<dim3(NKV / 32, DD / 32), blk>>>(wk, wkh, DD, NKV);
        transpose_h_kernel<<<dim3(NKV / 32, DD / 32), blk>>>(wv, wvh, DD, NKV);
        transpose_h_kernel<<<dim3(DD / 32, DD / 32), blk>>>(wo, woh, DD, DD);
    }

    cudaFuncSetAttribute(hgemm_kernel,
                         cudaFuncAttributeMaxDynamicSharedMemorySize, HG_SMEM);

    // QKV projections (fp16 tensor cores)
    hgemm_kernel<<<dim3(DD / 128, M / 128), 256, HG_SMEM>>>(hsh, wqh, qb, M, DD, DD);
    hgemm_kernel<<<dim3(NKV / 128, M / 128), 256, HG_SMEM>>>(hsh, wkh, kb, M, NKV, DD);
    hgemm_kernel<<<dim3(NKV / 128, M / 128), 256, HG_SMEM>>>(hsh, wvh, vb, M, NKV, DD);

    // RoPE -> fp16 (Q pre-scaled by 1/sqrt(HD)); V -> fp16 transposed
    {
        const float scale = 0.08838834764831845f;
        const int tq = BB * SS * HH * 64;
        rope_h_kernel<<<tq / 256, 256>>>(qb, qh, cosT, sinT, HH, scale);
        const int tk = BB * SS * KVHH * 64;
        rope_h_kernel<<<tk / 256, 256>>>(kb, kh, cosT, sinT, KVHH, 1.0f);
        dim3 blk(32, 8);
        vtrans_kernel<<<dim3(HDD / 32, SS / 32, BB * KVHH), blk>>>(vb, vt);
    }

    // Attention (fp16 tensor cores)
    {
        cudaFuncSetAttribute(attn_kernel,
                             cudaFuncAttributeMaxDynamicSharedMemorySize,
                             A_SMEM);
        dim3 ga(SS / 128, BB * HH);
        attn_kernel<<<ga, 256, A_SMEM>>>(qh, kh, vt, alibi, mask, cb);
    }

    // Output projection -> d_out (fp32)
    hgemm_kernel<<<dim3(DD / 128, M / 128), 256, HG_SMEM>>>(cb, woh, out, M, DD, DD);
}

// round 8
// speedup vs baseline: 6.9811x; 1.0936x over previous
#include <cuda_runtime.h>
#include <cuda_fp16.h>
#include <cstdint>
#include <cstddef>

// Problem constants
#define BB   2
#define SS   2048
#define DD   2048
#define HH   16
#define KVHH 4
#define HDD  128
#define GG   4   // H / KVH
#define NQKV 3072   // 2048 q + 512 k + 512 v

// ---------------------------------------------------------------------------
// Scratch (device globals — no allocations allowed)
// ---------------------------------------------------------------------------
__device__ float  g_qkv[BB * SS * NQKV];          // fused QKV fp32 out
__device__ __half g_qh[BB * SS * HH * HDD];       // post-rope fp16
__device__ __half g_kh[BB * SS * KVHH * HDD];
__device__ __half g_vt[BB * KVHH * HDD * SS];     // V^T per head: [b][kh][hd][s]
__device__ __half g_ctx[BB * SS * HH * HDD];
__device__ __half g_hs_h[BB * SS * DD];
__device__ __half g_wqkv_h[NQKV * DD];            // [wq|wk|wv]^T : [N][K]
__device__ __half g_wo_h[DD * DD];

// ---------------------------------------------------------------------------
// helpers
// ---------------------------------------------------------------------------
__device__ __forceinline__ void mma16x8x16(float* c, const uint32_t* a,
                                           const uint32_t* b) {
    asm volatile(
        "mma.sync.aligned.m16n8k16.row.col.f32.f16.f16.f32 "
        "{%0,%1,%2,%3}, {%4,%5,%6,%7}, {%8,%9}, {%0,%1,%2,%3};\n"
        : "+f"(c[0]), "+f"(c[1]), "+f"(c[2]), "+f"(c[3])
        : "r"(a[0]), "r"(a[1]), "r"(a[2]), "r"(a[3]), "r"(b[0]), "r"(b[1]));
}

__device__ __forceinline__ void cp16(uint32_t dst, const void* src) {
    asm volatile("cp.async.cg.shared.global [%0], [%1], 16;\n"
                 :: "r"(dst), "l"(src));
}
__device__ __forceinline__ void cp_commit() {
    asm volatile("cp.async.commit_group;\n");
}
template <int N>
__device__ __forceinline__ void cp_wait() {
    asm volatile("cp.async.wait_group %0;\n" :: "n"(N));
}

// ---------------------------------------------------------------------------
// pre-processing kernels
// ---------------------------------------------------------------------------
__global__ void f2h_kernel(const float4* __restrict__ src,
                           uint2* __restrict__ dst, int n4)
{
    for (int i = blockIdx.x * blockDim.x + threadIdx.x; i < n4;
         i += gridDim.x * blockDim.x) {
        const float4 v = src[i];
        const __half2 lo = __floats2half2_rn(v.x, v.y);
        const __half2 hi = __floats2half2_rn(v.z, v.w);
        uint2 u;
        u.x = *(const uint32_t*)&lo;
        u.y = *(const uint32_t*)&hi;
        dst[i] = u;
    }
}

// dst_h[C][R] = (half)src[R][C]; grid (C/32, R/32), block (32,8)
__global__ void transpose_h_kernel(const float* __restrict__ src,
                                   __half* __restrict__ dst, int R, int C)
{
    __shared__ float t[32][33];
    const int c0 = blockIdx.x * 32;
    const int r0 = blockIdx.y * 32;
    const int tx = threadIdx.x, ty = threadIdx.y;
    #pragma unroll
    for (int i = 0; i < 4; i++)
        t[ty + 8 * i][tx] = src[(size_t)(r0 + ty + 8 * i) * C + c0 + tx];
    __syncthreads();
    #pragma unroll
    for (int i = 0; i < 4; i++)
        dst[(size_t)(c0 + ty + 8 * i) * R + r0 + tx] =
            __float2half(t[tx][ty + 8 * i]);
}

// RoPE: fused-qkv fp32 in (row stride NQKV, col offset) -> fp16 out.
__global__ void rope_h_kernel(const float* __restrict__ x, int coff,
                              __half* __restrict__ y,
                              const float* __restrict__ cosT,
                              const float* __restrict__ sinT, int heads,
                              float scale)
{
    const int idx  = blockIdx.x * blockDim.x + threadIdx.x;
    const int half = idx & 63;
    const int h    = (idx >> 6) % heads;
    const int s    = (idx / (64 * heads)) % SS;
    const int b    = idx / (64 * heads * SS);

    const size_t sbase = (size_t)(b * SS + s) * NQKV + coff + h * HDD;
    const float x1 = x[sbase + half];
    const float x2 = x[sbase + half + 64];
    const float c1 = cosT[s * HDD + half];
    const float s1 = sinT[s * HDD + half];
    const float c2 = cosT[s * HDD + half + 64];
    const float s2 = sinT[s * HDD + half + 64];
    const size_t dbase = (size_t)((b * SS + s) * heads + h) * HDD;
    y[dbase + half]      = __float2half((x1 * c1 - x2 * s1) * scale);
    y[dbase + half + 64] = __float2half((x2 * c2 + x1 * s2) * scale);
}

// V (in fused qkv, col offset 2560) -> Vt [b][kvh][hd][s] fp16
__global__ void vtrans_kernel(const float* __restrict__ qkv,
                              __half* __restrict__ vt)
{
    __shared__ float t[32][33];
    const int hd0 = blockIdx.x * 32;
    const int s0  = blockIdx.y * 32;
    const int bk  = blockIdx.z;
    const int b   = bk / KVHH;
    const int kh  = bk % KVHH;
    const int tx = threadIdx.x, ty = threadIdx.y;
    #pragma unroll
    for (int i = 0; i < 4; i++)
        t[ty + 8 * i][tx] =
            qkv[(size_t)(b * SS + s0 + ty + 8 * i) * NQKV + 2560 + kh * HDD
                + hd0 + tx];
    __syncthreads();
    #pragma unroll
    for (int i = 0; i < 4; i++)
        vt[((size_t)(b * KVHH + kh) * HDD + hd0 + ty + 8 * i) * SS + s0 + tx] =
            __float2half(t[tx][ty + 8 * i]);
}

// ---------------------------------------------------------------------------
// FP16 tensor-core GEMM: C[M,N](fp32) = Ah[M,K] @ Bth[N,K]^T.
// 128x256 CTA tile, BK=32, 4-stage cp.async, 256 threads, warp tile 64x64.
// smem strides 40 halfs (pad 8) -> conflict-free half2 frag loads.
// ---------------------------------------------------------------------------
#define HG_ASZ   10240                      // bytes: 128*40*2
#define HG_BSZ   20480                      // bytes: 256*40*2
#define HG_STG   (HG_ASZ + HG_BSZ)          // 30720
#define HG_SMEM  (4 * HG_STG)               // 122880

__global__ __launch_bounds__(256, 1) void hgemm_kernel(
    const __half* __restrict__ A, const __half* __restrict__ Bt,
    float* __restrict__ C, int M, int N, int K)
{
    extern __shared__ char gsm[];
    uint32_t sbase;
    asm("{ .reg .u64 t; cvta.to.shared.u64 t, %1; cvt.u32.u64 %0, t; }"
        : "=r"(sbase) : "l"(gsm));

    const int tid  = threadIdx.x;
    const int lane = tid & 31;
    const int warp = tid >> 5;
    const int wm   = (warp >> 2) * 64;   // 0 or 64
    const int wn   = (warp & 3) * 64;    // 0,64,128,192
    const int grp  = lane >> 2;
    const int qid  = lane & 3;
    const int bm   = blockIdx.y * 128;
    const int bn   = blockIdx.x * 256;

    float c[4][8][4];
    #pragma unroll
    for (int mi = 0; mi < 4; mi++)
        #pragma unroll
        for (int ni = 0; ni < 8; ni++)
            #pragma unroll
            for (int r = 0; r < 4; r++) c[mi][ni][r] = 0.f;

    const int T = K / 32;

    auto issue = [&](int st) {
        const int s = st & 3;
        const uint32_t as = sbase + s * HG_STG;
        const uint32_t bs = as + HG_ASZ;
        const int k0 = st * 32;
        #pragma unroll
        for (int i = 0; i < 2; i++) {
            const int ch = tid + i * 256;     // 0..511
            const int r  = ch >> 2;           // 0..127
            const int c8 = (ch & 3) << 3;     // 0,8,16,24 halfs
            cp16(as + (r * 40 + c8) * 2, A + (size_t)(bm + r) * K + k0 + c8);
        }
        #pragma unroll
        for (int i = 0; i < 4; i++) {
            const int ch = tid + i * 256;     // 0..1023
            const int r  = ch >> 2;           // 0..255
            const int c8 = (ch & 3) << 3;
            cp16(bs + (r * 40 + c8) * 2, Bt + (size_t)(bn + r) * K + k0 + c8);
        }
        cp_commit();
    };

    issue(0);
    issue(1);
    issue(2);

    for (int t = 0; t < T; t++) {
        if (t < T - 2)       cp_wait<2>();
        else if (t == T - 2) cp_wait<1>();
        else                 cp_wait<0>();
        __syncthreads();
        if (t + 3 < T) issue(t + 3);

        const uint32_t* As32 = (const uint32_t*)(gsm + (t & 3) * HG_STG);
        const uint32_t* Bs32 = (const uint32_t*)(gsm + (t & 3) * HG_STG + HG_ASZ);
        #pragma unroll
        for (int kk2 = 0; kk2 < 16; kk2 += 8) {   // two k16 steps (u32 units)
            uint32_t a[4][4], bf[8][2];
            #pragma unroll
            for (int mi = 0; mi < 4; mi++) {
                const int m = wm + mi * 16 + grp;
                a[mi][0] = As32[m * 20 + kk2 + qid];
                a[mi][1] = As32[(m + 8) * 20 + kk2 + qid];
                a[mi][2] = As32[m * 20 + kk2 + qid + 4];
                a[mi][3] = As32[(m + 8) * 20 + kk2 + qid + 4];
            }
            #pragma unroll
            for (int ni = 0; ni < 8; ni++) {
                const int n = wn + ni * 8 + grp;
                bf[ni][0] = Bs32[n * 20 + kk2 + qid];
                bf[ni][1] = Bs32[n * 20 + kk2 + qid + 4];
            }
            #pragma unroll
            for (int mi = 0; mi < 4; mi++)
                #pragma unroll
                for (int ni = 0; ni < 8; ni++)
                    mma16x8x16(c[mi][ni], a[mi], bf[ni]);
        }
        __syncthreads();
    }

    #pragma unroll
    for (int mi = 0; mi < 4; mi++) {
        const int row0 = bm + wm + mi * 16 + grp;
        #pragma unroll
        for (int ni = 0; ni < 8; ni++) {
            const int col = bn + wn + ni * 8 + qid * 2;
            *(float2*)&C[(size_t)row0 * N + col] =
                make_float2(c[mi][ni][0], c[mi][ni][1]);
            *(float2*)&C[(size_t)(row0 + 8) * N + col] =
                make_float2(c[mi][ni][2], c[mi][ni][3]);
        }
    }
}

// ---------------------------------------------------------------------------
// FP16 flash attention. BM=128, BN=128, 8 warps (16 q rows each).
// Q [128][136]h, K 2x[128][136]h, Vt [128][136]h, P [128][136]h.
// Heavy CTAs launch first (bx reversed). Warp-local softmax.
// ---------------------------------------------------------------------------
#define AT_Q    0
#define AT_K    34816                        // 128*136*2
#define AT_KSTG 34816
#define AT_V    104448
#define AT_SC   139264
#define AT_SMEM 174080

__global__ __launch_bounds__(256, 1) void attn_kernel(
    const __half* __restrict__ q, const __half* __restrict__ k,
    const __half* __restrict__ vt, const float* __restrict__ alibi,
    const float* __restrict__ mask, __half* __restrict__ ctx)
{
    extern __shared__ char asm_raw[];
    uint32_t* S32 = (uint32_t*)asm_raw;
    uint32_t sbase;
    asm("{ .reg .u64 t; cvta.to.shared.u64 t, %1; cvt.u32.u64 %0, t; }"
        : "=r"(sbase) : "l"(asm_raw));

    uint32_t* Q32  = S32;                   // stride 68 u32
    uint32_t* K32  = S32 + AT_K / 4;        // 2 stages, stride 68
    uint32_t* Vt32 = S32 + AT_V / 4;        // stride 68
    uint32_t* Sc32 = S32 + AT_SC / 4;       // stride 68

    const int tid  = threadIdx.x;
    const int lane = tid & 31;
    const int warp = tid >> 5;
    const int grp  = lane >> 2;
    const int qid  = lane & 3;
    const int bxr  = gridDim.x - 1 - blockIdx.x;   // heavy first
    const int bh   = blockIdx.y;
    const int b    = bh / HH;
    const int h    = bh % HH;
    const int kh   = h / GG;
    const int q0   = bxr * 128;
    const int rl   = warp * 16 + grp;

    const int ntiles = bxr + 1;

    // prologue: group1 = Q + K[0], group2 = Vt[0]
    #pragma unroll
    for (int i = 0; i < 8; i++) {
        const int ch = tid + i * 256;       // 0..2047
        const int r  = ch >> 4;             // 0..127
        const int c8 = (ch & 15) << 3;      // halfs 0..120
        cp16(sbase + AT_Q + (r * 136 + c8) * 2,
             q + (size_t)((b * SS + q0 + r) * HH + h) * HDD + c8);
    }
    #pragma unroll
    for (int i = 0; i < 8; i++) {
        const int ch = tid + i * 256;
        const int r  = ch >> 4;
        const int c8 = (ch & 15) << 3;
        cp16(sbase + AT_K + (r * 136 + c8) * 2,
             k + (size_t)((b * SS + r) * KVHH + kh) * HDD + c8);
    }
    cp_commit();
    #pragma unroll
    for (int i = 0; i < 8; i++) {
        const int ch = tid + i * 256;
        const int r  = ch >> 4;             // hd 0..127
        const int c8 = (ch & 15) << 3;      // kv halfs 0..120
        cp16(sbase + AT_V + (r * 136 + c8) * 2,
             vt + ((size_t)(b * KVHH + kh) * HDD + r) * SS + c8);
    }
    cp_commit();

    float o[16][4];
    #pragma unroll
    for (int ni = 0; ni < 16; ni++)
        #pragma unroll
        for (int r = 0; r < 4; r++) o[ni][r] = 0.f;
    float m0 = -1e30f, m1 = -1e30f, l0 = 0.f, l1 = 0.f;

    const int rg0 = q0 + rl;
    const int rg1 = rg0 + 8;

    for (int t = 0; t < ntiles; t++) {
        const int kv0 = t * 128;
        const int pk  = t & 1;

        cp_wait<1>();               // K[t] (and Q on t=0) ready
        __syncthreads();

        if (t + 1 < ntiles) {       // prefetch K[t+1]
            const int kv1 = kv0 + 128;
            #pragma unroll
            for (int i = 0; i < 8; i++) {
                const int ch = tid + i * 256;
                const int r  = ch >> 4;
                const int c8 = (ch & 15) << 3;
                cp16(sbase + AT_K + ((t + 1) & 1) * AT_KSTG + (r * 136 + c8) * 2,
                     k + (size_t)((b * SS + kv1 + r) * KVHH + kh) * HDD + c8);
            }
            cp_commit();
        }

        // ---- scores: 16x128 warp tile, k16 steps ----
        float sf[16][4];
        #pragma unroll
        for (int ni = 0; ni < 16; ni++)
            #pragma unroll
            for (int r = 0; r < 4; r++) sf[ni][r] = 0.f;

        const uint32_t* Kb = K32 + pk * (AT_KSTG / 4);
        #pragma unroll
        for (int kk2 = 0; kk2 < 64; kk2 += 8) {     // HD/2 u32
            uint32_t a[4];
            a[0] = Q32[rl * 68 + kk2 + qid];
            a[1] = Q32[(rl + 8) * 68 + kk2 + qid];
            a[2] = Q32[rl * 68 + kk2 + qid + 4];
            a[3] = Q32[(rl + 8) * 68 + kk2 + qid + 4];
            #pragma unroll
            for (int ni = 0; ni < 16; ni++) {
                const int n = ni * 8 + grp;
                uint32_t bf[2] = { Kb[n * 68 + kk2 + qid],
                                   Kb[n * 68 + kk2 + qid + 4] };
                mma16x8x16(sf[ni], a, bf);
            }
        }

        // ---- bias + causal (direct loads; ptxas hoists LDGs) ----
        const bool diag = (t == ntiles - 1);
        #pragma unroll
        for (int ni = 0; ni < 16; ni++) {
            const int cg = kv0 + ni * 8 + 2 * qid;
            const float2 mk  = *(const float2*)(mask + b * SS + cg);
            const float2 a0  = *(const float2*)(alibi + ((size_t)b * SS + rg0) * SS + cg);
            const float2 a1  = *(const float2*)(alibi + ((size_t)b * SS + rg1) * SS + cg);
            sf[ni][0] += a0.x + mk.x;
            sf[ni][1] += a0.y + mk.y;
            sf[ni][2] += a1.x + mk.x;
            sf[ni][3] += a1.y + mk.y;
            if (diag) {
                if (cg > rg0)     sf[ni][0] = -1e30f;
                if (cg + 1 > rg0) sf[ni][1] = -1e30f;
                if (cg > rg1)     sf[ni][2] = -1e30f;
                if (cg + 1 > rg1) sf[ni][3] = -1e30f;
            }
        }

        // ---- warp-local online softmax ----
        float mx0 = -1e30f, mx1 = -1e30f;
        #pragma unroll
        for (int ni = 0; ni < 16; ni++) {
            mx0 = fmaxf(mx0, fmaxf(sf[ni][0], sf[ni][1]));
            mx1 = fmaxf(mx1, fmaxf(sf[ni][2], sf[ni][3]));
        }
        mx0 = fmaxf(mx0, __shfl_xor_sync(0xffffffffu, mx0, 1));
        mx0 = fmaxf(mx0, __shfl_xor_sync(0xffffffffu, mx0, 2));
        mx1 = fmaxf(mx1, __shfl_xor_sync(0xffffffffu, mx1, 1));
        mx1 = fmaxf(mx1, __shfl_xor_sync(0xffffffffu, mx1, 2));

        const float nm0 = fmaxf(m0, mx0);
        const float nm1 = fmaxf(m1, mx1);
        const float f0  = __expf(m0 - nm0);
        const float f1  = __expf(m1 - nm1);
        float ls0 = 0.f, ls1 = 0.f;
        #pragma unroll
        for (int ni = 0; ni < 16; ni++) {
            const float p0 = __expf(sf[ni][0] - nm0);
            const float p1 = __expf(sf[ni][1] - nm0);
            const float p2 = __expf(sf[ni][2] - nm1);
            const float p3 = __expf(sf[ni][3] - nm1);
            ls0 += p0 + p1;
            ls1 += p2 + p3;
            const __half2 hp0 = __floats2half2_rn(p0, p1);
            const __half2 hp1 = __floats2half2_rn(p2, p3);
            Sc32[rl * 68 + ni * 4 + qid]       = *(const uint32_t*)&hp0;
            Sc32[(rl + 8) * 68 + ni * 4 + qid] = *(const uint32_t*)&hp1;
        }
        ls0 += __shfl_xor_sync(0xffffffffu, ls0, 1);
        ls0 += __shfl_xor_sync(0xffffffffu, ls0, 2);
        ls1 += __shfl_xor_sync(0xffffffffu, ls1, 1);
        ls1 += __shfl_xor_sync(0xffffffffu, ls1, 2);
        l0 = l0 * f0 + ls0;  m0 = nm0;
        l1 = l1 * f1 + ls1;  m1 = nm1;

        #pragma unroll
        for (int ni = 0; ni < 16; ni++) {
            o[ni][0] *= f0; o[ni][1] *= f0;
            o[ni][2] *= f1; o[ni][3] *= f1;
        }
        __syncwarp();

        // Vt[t] complete + visible
        if (t + 1 < ntiles) cp_wait<1>();
        else                cp_wait<0>();
        __syncthreads();

        // ---- PV: 16x128 warp tile, k16 over kv=128 ----
        #pragma unroll
        for (int kk2 = 0; kk2 < 64; kk2 += 8) {
            uint32_t a[4];
            a[0] = Sc32[rl * 68 + kk2 + qid];
            a[1] = Sc32[(rl + 8) * 68 + kk2 + qid];
            a[2] = Sc32[rl * 68 + kk2 + qid + 4];
            a[3] = Sc32[(rl + 8) * 68 + kk2 + qid + 4];
            #pragma unroll
            for (int ni = 0; ni < 16; ni++) {
                const int n = ni * 8 + grp;            // hd row of Vt
                uint32_t bf[2] = { Vt32[n * 68 + kk2 + qid],
                                   Vt32[n * 68 + kk2 + qid + 4] };
                mma16x8x16(o[ni], a, bf);
            }
        }
        __syncthreads();

        if (t + 1 < ntiles) {       // prefetch Vt[t+1]
            const int kv1 = kv0 + 128;
            #pragma unroll
            for (int i = 0; i < 8; i++) {
                const int ch = tid + i * 256;
                const int r  = ch >> 4;
                const int c8 = (ch & 15) << 3;
                cp16(sbase + AT_V + (r * 136 + c8) * 2,
                     vt + ((size_t)(b * KVHH + kh) * HDD + r) * SS + kv1 + c8);
            }
            cp_commit();
        }
    }

    // epilogue
    const float il0 = 1.f / l0;
    const float il1 = 1.f / l1;
    #pragma unroll
    for (int ni = 0; ni < 16; ni++) {
        const int col = ni * 8 + 2 * qid;
        __half* d0 = ctx + (size_t)((b * SS + rg0) * HH + h) * HDD + col;
        __half* d1 = ctx + (size_t)((b * SS + rg1) * HH + h) * HDD + col;
        *(__half2*)d0 = __floats2half2_rn(o[ni][0] * il0, o[ni][1] * il0);
        *(__half2*)d1 = __floats2half2_rn(o[ni][2] * il1, o[ni][3] * il1);
    }
}

// ---------------------------------------------------------------------------
// Launch
// ---------------------------------------------------------------------------
extern "C" void kernel_launch(void* const* d_in, const int* in_sizes, int n_in,
                              void* d_out, int out_size)
{
    const float* hs    = (const float*)d_in[0];
    const float* cosT  = (const float*)d_in[1];
    const float* sinT  = (const float*)d_in[2];
    const float* alibi = (const float*)d_in[3];
    const float* mask  = (const float*)d_in[4];
    const float* wq    = (const float*)d_in[5];
    const float* wk    = (const float*)d_in[6];
    const float* wv    = (const float*)d_in[7];
    const float* wo    = (const float*)d_in[8];
    float* out = (float*)d_out;

    float  *qkv;
    __half *qh, *kh, *vt, *cb, *hsh, *wqkvh, *woh;
    cudaGetSymbolAddress((void**)&qkv,   g_qkv);
    cudaGetSymbolAddress((void**)&qh,    g_qh);
    cudaGetSymbolAddress((void**)&kh,    g_kh);
    cudaGetSymbolAddress((void**)&vt,    g_vt);
    cudaGetSymbolAddress((void**)&cb,    g_ctx);
    cudaGetSymbolAddress((void**)&hsh,   g_hs_h);
    cudaGetSymbolAddress((void**)&wqkvh, g_wqkv_h);
    cudaGetSymbolAddress((void**)&woh,   g_wo_h);

    const int M   = BB * SS;     // 4096
    const int NKV = KVHH * HDD;  // 512

    // fp16 conversion / weight transposes into fused [N][K] buffer
    f2h_kernel<<<1024, 256>>>((const float4*)hs, (uint2*)hsh, BB * SS * DD / 4);
    {
        dim3 blk(32, 8);
        transpose_h_kernel<<<dim3(DD / 32, DD / 32), blk>>>(wq, wqkvh, DD, DD);
        transpose_h_kernel<<<dim3(NKV / 32, DD / 32), blk>>>(
            wk, wqkvh + (size_t)DD * DD, DD, NKV);
        transpose_h_kernel<<<dim3(NKV / 32, DD / 32), blk>>>(
            wv, wqkvh + (size_t)(DD + NKV) * DD, DD, NKV);
        transpose_h_kernel<<<dim3(DD / 32, DD / 32), blk>>>(wo, woh, DD, DD);
    }

    cudaFuncSetAttribute(hgemm_kernel,
                         cudaFuncAttributeMaxDynamicSharedMemorySize, HG_SMEM);

    // Fused QKV projection (fp16 tensor cores, 128x256 tiles)
    hgemm_kernel<<<dim3(NQKV / 256, M / 128), 256, HG_SMEM>>>(
        hsh, wqkvh, qkv, M, NQKV, DD);

    // RoPE -> fp16 (Q pre-scaled by 1/sqrt(HD)); V -> fp16 transposed
    {
        const float scale = 0.08838834764831845f;
        const int tq = BB * SS * HH * 64;
        rope_h_kernel<<<tq / 256, 256>>>(qkv, 0, qh, cosT, sinT, HH, scale);
        const int tk = BB * SS * KVHH * 64;
        rope_h_kernel<<<tk / 256, 256>>>(qkv, DD, kh, cosT, sinT, KVHH, 1.0f);
        dim3 blk(32, 8);
        vtrans_kernel<<<dim3(HDD / 32, SS / 32, BB * KVHH), blk>>>(qkv, vt);
    }

    // Attention (fp16 tensor cores, BN=128, heavy-first)
    {
        cudaFuncSetAttribute(attn_kernel,
                             cudaFuncAttributeMaxDynamicSharedMemorySize,
                             AT_SMEM);
        dim3 ga(SS / 128, BB * HH);
        attn_kernel<<<ga, 256, AT_SMEM>>>(qh, kh, vt, alibi, mask, cb);
    }

    // Output projection -> d_out (fp32)
    hgemm_kernel<<<dim3(DD / 256, M / 128), 256, HG_SMEM>>>(
        cb, woh, out, M, DD, DD);
}